// round 10
// baseline (speedup 1.0000x reference)
#include <cuda_runtime.h>
#include <cuda_bf16.h>

// ---------------------------------------------------------------------------
// Problem constants
// ---------------------------------------------------------------------------
#define LAYERS 4
#define NC 3
#define D1 48
#define D2 48
#define D3 48
#define D4 24
#define NROW (D1*D2*D3)           // 110,592 x4-rows per channel
#define NSP  (D1*D2*D3*D4)        // 2,654,208 spatial points per channel
#define CN   (NC*NSP)             // 7,962,624 elems per batch image

// Scratch: batch-interleaved tensors, float2 = {b0, b1}
__device__ float2 s_fi[CN];
__device__ float2 s_bi[CN];
__device__ float2 s_g [CN];
__device__ float2 s_t [CN];
__device__ float2 s_oA[CN];
__device__ float2 s_oB[CN];
// x4-Winograd-transformed inputs: [ci 0..5][row][group*8+point] f2
__device__ float2 s_u[6*(size_t)NROW*32];
// Winograd-transformed Wg weights, scalar: [L][ci][k123][co*8+p]
__device__ float s_wgtf[LAYERS*6*27*24];

// ---- packed f32x2 ops ------------------------------------------------------
__device__ __forceinline__ float2 ffma2(float2 a, float2 b, float2 c) {
    unsigned long long ua, ub, uc, ud;
    ua = *reinterpret_cast<const unsigned long long*>(&a);
    ub = *reinterpret_cast<const unsigned long long*>(&b);
    uc = *reinterpret_cast<const unsigned long long*>(&c);
    asm("fma.rn.f32x2 %0, %1, %2, %3;" : "=l"(ud) : "l"(ua), "l"(ub), "l"(uc));
    return *reinterpret_cast<float2*>(&ud);
}
__device__ __forceinline__ float2 fadd2(float2 a, float2 b) {
    unsigned long long ua, ub, ud;
    ua = *reinterpret_cast<const unsigned long long*>(&a);
    ub = *reinterpret_cast<const unsigned long long*>(&b);
    asm("add.rn.f32x2 %0, %1, %2;" : "=l"(ud) : "l"(ua), "l"(ub));
    return *reinterpret_cast<float2*>(&ud);
}
__device__ __forceinline__ float2 fsub2(float2 a, float2 b) {   // a - b
    return ffma2(b, make_float2(-1.f, -1.f), a);
}

// ---------------------------------------------------------------------------
// Pack (+ folded Wg weight transform: G w, F(6,3) points {0,±1,±2,±1/2,inf})
// ---------------------------------------------------------------------------
__global__ void pack_kernel(const float4* __restrict__ f,
                            const float4* __restrict__ bnd,
                            float4* __restrict__ fi,
                            float4* __restrict__ bi,
                            const float* __restrict__ Wg,
                            float* __restrict__ wtf) {
    int i = blockIdx.x * blockDim.x + threadIdx.x;
    if (i < LAYERS*6*27*3) {                 // weight transform (1944 threads)
        int co = i % 3;  int r = i / 3;
        int k123 = r % 27; r /= 27;
        int ci = r % 6;    int L = r / 6;
        const float* w = Wg + L*1458 + (co*6 + ci)*81 + k123*3;
        float w0 = w[0], w1 = w[1], w2 = w[2];
        float p[8];
        p[0] = w0;
        p[1] = (-2.f/9.f)  * (w0 + w1 + w2);
        p[2] = (-2.f/9.f)  * (w0 - w1 + w2);
        p[3] = (1.f/90.f)*w0 + (1.f/45.f)*w1 + (2.f/45.f)*w2;
        p[4] = (1.f/90.f)*w0 - (1.f/45.f)*w1 + (2.f/45.f)*w2;
        p[5] = (32.f/45.f)*w0 + (16.f/45.f)*w1 + (8.f/45.f)*w2;
        p[6] = (32.f/45.f)*w0 - (16.f/45.f)*w1 + (8.f/45.f)*w2;
        p[7] = w2;
        float* o = wtf + ((L*6 + ci)*27 + k123)*24 + co*8;
        #pragma unroll
        for (int m = 0; m < 8; ++m) o[m] = p[m];
    }
    if (i >= CN / 4) return;
    float4 a = f[i],   b = f[i + CN / 4];
    fi[2*i]     = make_float4(a.x, b.x, a.y, b.y);
    fi[2*i + 1] = make_float4(a.z, b.z, a.w, b.w);
    a = bnd[i]; b = bnd[i + CN / 4];
    bi[2*i]     = make_float4(a.x, b.x, a.y, b.y);
    bi[2*i + 1] = make_float4(a.z, b.z, a.w, b.w);
}

// ---------------------------------------------------------------------------
// x4 input transform (B^T), 3 channels per call, global -> global.
// [UNCHANGED — R9 passing]
// ---------------------------------------------------------------------------
__global__ __launch_bounds__(256) void bx_kernel(
    const float2* __restrict__ src,   // 3 channels, [ch][row][24] f2
    float2* __restrict__ dst)         // 3 channels, [ch][row][32] f2
{
    __shared__ float4 sraw[64*13];
    const int ch   = blockIdx.y;
    const int row0 = blockIdx.x * 64;
    const float4* s = (const float4*)(src + (size_t)ch*NSP + (size_t)row0*D4);
    for (int idx = threadIdx.x; idx < 768; idx += 256) {
        int r = idx / 12, c = idx % 12;
        sraw[r*13 + c] = s[idx];
    }
    __syncthreads();

    const int r = threadIdx.x >> 2, g = threadIdx.x & 3;
    const float2* rp = (const float2*)&sraw[r*13];
    const float2 z = make_float2(0.f, 0.f);
    float2 x[8];
    #pragma unroll
    for (int e = 0; e < 8; ++e) {
        int x4 = 6*g - 1 + e;
        x[e] = ((unsigned)x4 < (unsigned)D4) ? rp[x4] : z;
    }
    float2 u[8];
    u[0] = ffma2(fsub2(x[4], x[2]), make_float2(5.25f,5.25f), fsub2(x[0], x[6]));
    u[7] = ffma2(fsub2(x[3], x[5]), make_float2(5.25f,5.25f), fsub2(x[7], x[1]));
    {
        float2 e = ffma2(x[4], make_float2(-4.25f,-4.25f), fadd2(x[2], x[6]));
        float2 o = ffma2(x[3], make_float2(-4.25f,-4.25f), fadd2(x[1], x[5]));
        u[1] = fadd2(e, o);
        u[2] = fsub2(e, o);
    }
    {
        float2 e = ffma2(x[2], make_float2(0.25f,0.25f),
                   ffma2(x[4], make_float2(-1.25f,-1.25f), x[6]));
        float2 o = ffma2(x[1], make_float2(0.5f,0.5f),
                   ffma2(x[3], make_float2(-2.5f,-2.5f),
                   ffma2(x[5], make_float2(2.f,2.f), z)));
        u[3] = fadd2(e, o);
        u[4] = fsub2(e, o);
    }
    {
        float2 e = ffma2(x[2], make_float2(4.f,4.f),
                   ffma2(x[4], make_float2(-5.f,-5.f), x[6]));
        float2 o = ffma2(x[1], make_float2(2.f,2.f),
                   ffma2(x[3], make_float2(-2.5f,-2.5f),
                   ffma2(x[5], make_float2(0.5f,0.5f), z)));
        u[5] = fadd2(e, o);
        u[6] = fsub2(e, o);
    }
    float4* d = (float4*)(dst + ((size_t)(ch*NROW + row0 + r))*32) + g*4;
    #pragma unroll
    for (int m = 0; m < 4; ++m)
        d[m] = make_float4(u[2*m].x, u[2*m].y, u[2*m+1].x, u[2*m+1].y);
}

// ---------------------------------------------------------------------------
// Wg conv in Winograd(x4) domain. Same dataflow as R9; inner loop split into
// two 4-point phases to shrink peak live registers, and 3 blocks/SM forced
// (85-reg cap) to lift occupancy to ~36 % against the crossbar latency.
// ---------------------------------------------------------------------------
#define WG_SMEM (240*17*16 + 648*4)   // 65280 + 2592 = 67872 B -> 3 blocks/SM

__global__ __launch_bounds__(256, 3) void wg_kernel(
    const float2* __restrict__ ubuf,  // 6 ch transformed
    const float*  __restrict__ wgt,   // this layer: [ci][k123][co*8+p]
    const float*  __restrict__ bias,
    float2* __restrict__ out)
{
    extern __shared__ float4 dsm4[];
    float4* sIn = dsm4;                       // [240][17]
    float*  sWf = (float*)(dsm4 + 240*17);    // [27][24]

    const int tid = threadIdx.x;
    const int x3l = tid & 7;
    const int q   = (tid >> 3) & 3;
    const int x2l = (tid >> 5) & 3;
    const int x1l = tid >> 7;
    const int x1g = blockIdx.x * 2;
    const int x2g = blockIdx.y * 4;
    const int x3g = blockIdx.z * 8;

    float2 acc[3][8];
    #pragma unroll
    for (int co = 0; co < 3; ++co)
        #pragma unroll
        for (int m = 0; m < 8; ++m) acc[co][m] = make_float2(0.f, 0.f);

    for (int ci = 0; ci < 6; ++ci) {
        const float4* __restrict__ usrc =
            (const float4*)(ubuf + (size_t)ci*NROW*32);
        __syncthreads();
        // weights for this ci: 648 floats = 162 f4
        {
            const float4* wsrc = (const float4*)(wgt + ci*648);
            for (int s = tid; s < 162; s += 256)
                ((float4*)sWf)[s] = wsrc[s];
        }
        // stage 240 transformed rows (16 f4 each), zero outside volume
        for (int idx = tid; idx < 240*16; idx += 256) {
            int r = idx >> 4, c = idx & 15;
            int p3 = r % 10; int t = r / 10; int p2 = t % 6; int p1 = t / 6;
            int g1 = x1g - 1 + p1, g2 = x2g - 1 + p2, g3 = x3g - 1 + p3;
            float4 v = make_float4(0.f, 0.f, 0.f, 0.f);
            if ((unsigned)g1 < (unsigned)D1 && (unsigned)g2 < (unsigned)D2 &&
                (unsigned)g3 < (unsigned)D3)
                v = usrc[(size_t)((g1*D2 + g2)*D3 + g3)*16 + c];
            sIn[r*17 + c] = v;
        }
        __syncthreads();

        #pragma unroll 1
        for (int k1 = 0; k1 < 3; ++k1) {
            #pragma unroll
            for (int k23 = 0; k23 < 9; ++k23) {
                const int k2 = k23 / 3, k3 = k23 % 3;
                const float4* up = sIn
                    + (((x1l + k1)*6 + (x2l + k2))*10 + (x3l + k3))*17 + q*4;
                const float4* wp = (const float4*)(sWf + (k1*9 + k23)*24);

                // phase A: transformed points 0..3
                {
                    float4 ua = up[0], ub = up[1];
                    float2 u0 = make_float2(ua.x, ua.y);
                    float2 u1 = make_float2(ua.z, ua.w);
                    float2 u2 = make_float2(ub.x, ub.y);
                    float2 u3 = make_float2(ub.z, ub.w);
                    #pragma unroll
                    for (int co = 0; co < 3; ++co) {
                        float4 w = wp[co*2];
                        acc[co][0] = ffma2(u0, make_float2(w.x,w.x), acc[co][0]);
                        acc[co][1] = ffma2(u1, make_float2(w.y,w.y), acc[co][1]);
                        acc[co][2] = ffma2(u2, make_float2(w.z,w.z), acc[co][2]);
                        acc[co][3] = ffma2(u3, make_float2(w.w,w.w), acc[co][3]);
                    }
                }
                // phase B: transformed points 4..7
                {
                    float4 ua = up[2], ub = up[3];
                    float2 u4 = make_float2(ua.x, ua.y);
                    float2 u5 = make_float2(ua.z, ua.w);
                    float2 u6 = make_float2(ub.x, ub.y);
                    float2 u7 = make_float2(ub.z, ub.w);
                    #pragma unroll
                    for (int co = 0; co < 3; ++co) {
                        float4 w = wp[co*2 + 1];
                        acc[co][4] = ffma2(u4, make_float2(w.x,w.x), acc[co][4]);
                        acc[co][5] = ffma2(u5, make_float2(w.y,w.y), acc[co][5]);
                        acc[co][6] = ffma2(u6, make_float2(w.z,w.z), acc[co][6]);
                        acc[co][7] = ffma2(u7, make_float2(w.w,w.w), acc[co][7]);
                    }
                }
            }
        }
    }

    // inverse transform A^T m + bias (validated in R8/R9)
    const int x1 = x1g + x1l, x2 = x2g + x2l, x3 = x3g + x3l;
    const int base = ((x1*D2 + x2)*D3 + x3)*D4 + q*6;
    #pragma unroll
    for (int co = 0; co < 3; ++co) {
        float bsc = __ldg(bias + co);
        float2 bb = make_float2(bsc, bsc);
        float2* m = acc[co];
        float2 s1 = fadd2(m[1], m[2]), d1 = fsub2(m[1], m[2]);
        float2 s3 = fadd2(m[3], m[4]), d3 = fsub2(m[3], m[4]);
        float2 s5 = fadd2(m[5], m[6]), d5 = fsub2(m[5], m[6]);
        float2 y[6];
        y[0] = fadd2(fadd2(fadd2(m[0], s1), fadd2(s3, s5)), bb);
        y[1] = ffma2(d3, make_float2(2.f,2.f),
               ffma2(d5, make_float2(0.5f,0.5f), fadd2(d1, bb)));
        y[2] = ffma2(s3, make_float2(4.f,4.f),
               ffma2(s5, make_float2(0.25f,0.25f), fadd2(s1, bb)));
        y[3] = ffma2(d3, make_float2(8.f,8.f),
               ffma2(d5, make_float2(0.125f,0.125f), fadd2(d1, bb)));
        y[4] = ffma2(s3, make_float2(16.f,16.f),
               ffma2(s5, make_float2(0.0625f,0.0625f), fadd2(s1, bb)));
        y[5] = ffma2(d3, make_float2(32.f,32.f),
               ffma2(d5, make_float2(0.03125f,0.03125f),
               fadd2(fadd2(d1, m[7]), bb)));
        float4* op = (float4*)(out + co*NSP + base);
        #pragma unroll
        for (int j2 = 0; j2 < 3; ++j2)
            op[j2] = make_float4(y[2*j2].x, y[2*j2].y,
                                 y[2*j2+1].x, y[2*j2+1].y);
    }
}

// ---------------------------------------------------------------------------
// W1 conv: 3->3 ch, (3,3,3,1) taps, pad (1,1,1,0)  [UNCHANGED — R7 passing]
// ---------------------------------------------------------------------------
#define W1_W_F2     (81*4)
#define W1_STAGE_F2 (240*26)
#define W1_SMEM     ((W1_W_F2 + W1_STAGE_F2)*8)    // 52512 B

__global__ __launch_bounds__(256, 3) void w1_kernel(
    const float2* __restrict__ g,
    const float*  __restrict__ W,  const float* __restrict__ bias,
    float2* __restrict__ out)
{
    extern __shared__ float2 dsm[];
    float2* sW  = dsm;
    float2* sIn = dsm + W1_W_F2;

    const int tid = threadIdx.x;
    const int x3l = tid & 7;
    const int q   = (tid >> 3) & 3;
    const int x2l = (tid >> 5) & 3;
    const int x1l = tid >> 7;
    const int x1g = blockIdx.x * 2;
    const int x2g = blockIdx.y * 4;
    const int x3g = blockIdx.z * 8;

    for (int s = tid; s < 81*3; s += 256) {
        int grp = s / 3, co = s % 3;
        int ci = grp / 27, k = grp % 27;
        float w = W[(co*3 + ci)*27 + k];
        sW[grp*4 + co] = make_float2(w, w);
    }

    float2 acc[3][6];
    #pragma unroll
    for (int co = 0; co < 3; ++co) {
        float b = __ldg(bias + co);
        #pragma unroll
        for (int j = 0; j < 6; ++j) acc[co][j] = make_float2(b, b);
    }

    for (int ci = 0; ci < 3; ++ci) {
        const float2* __restrict__ src = g + ci * NSP;
        __syncthreads();
        for (int idx = tid; idx < 240*12; idx += 256) {
            int row = idx / 12, c = idx % 12;
            int p3 = row % 10; int t = row / 10; int p2 = t % 6; int p1 = t / 6;
            int g1 = x1g - 1 + p1, g2 = x2g - 1 + p2, g3 = x3g - 1 + p3;
            float4 v = make_float4(0.f, 0.f, 0.f, 0.f);
            if ((unsigned)g1 < (unsigned)D1 && (unsigned)g2 < (unsigned)D2 &&
                (unsigned)g3 < (unsigned)D3)
                v = ((const float4*)src)[((g1*D2 + g2)*D3 + g3)*12 + c];
            ((float4*)sIn)[row*13 + c] = v;
        }
        __syncthreads();

        const float2* wci = sW + ci * 108;
        #pragma unroll 1
        for (int k1 = 0; k1 < 3; ++k1) {
            #pragma unroll
            for (int k23 = 0; k23 < 9; ++k23) {
                const int k2 = k23 / 3, k3 = k23 % 3;
                const float4* ip = (const float4*)sIn
                    + (((x1l + k1)*6 + (x2l + k2))*10 + (x3l + k3))*13 + q*3;
                float4 a4[3];
                #pragma unroll
                for (int m = 0; m < 3; ++m) a4[m] = ip[m];
                const float2* uf = reinterpret_cast<const float2*>(a4);

                const float2* wp = wci + (k1*9 + k23)*4;
                float2 w0 = wp[0];
                float2 w1 = wp[1];
                float2 w2 = wp[2];
                #pragma unroll
                for (int j = 0; j < 6; ++j) {
                    acc[0][j] = ffma2(uf[j], w0, acc[0][j]);
                    acc[1][j] = ffma2(uf[j], w1, acc[1][j]);
                    acc[2][j] = ffma2(uf[j], w2, acc[2][j]);
                }
            }
        }
    }

    const int x1 = x1g + x1l, x2 = x2g + x2l, x3 = x3g + x3l;
    const int base = ((x1*D2 + x2)*D3 + x3)*D4 + q*6;
    #pragma unroll
    for (int co = 0; co < 3; ++co) {
        float4* op = (float4*)(out + co*NSP + base);
        #pragma unroll
        for (int j2 = 0; j2 < 3; ++j2)
            op[j2] = make_float4(acc[co][2*j2].x,   acc[co][2*j2].y,
                                 acc[co][2*j2+1].x, acc[co][2*j2+1].y);
    }
}

// ---------------------------------------------------------------------------
// Fused epilogue  [UNCHANGED — passing since R1]
// ---------------------------------------------------------------------------
__global__ void w2wd_kernel(
    const float2* __restrict__ t,  const float2* __restrict__ op,
    const float*  __restrict__ W2, const float* __restrict__ b2,
    const float*  __restrict__ Wd, const float* __restrict__ bd,
    float2* __restrict__ onew, float* __restrict__ ofinal, int final_layer)
{
    int i = blockIdx.x * blockDim.x + threadIdx.x;
    if (i >= NSP) return;
    int x4 = i % D4;

    float w2r[3][3][3], wdr[3][3];
    #pragma unroll
    for (int co = 0; co < 3; ++co) {
        #pragma unroll
        for (int ci = 0; ci < 3; ++ci) {
            #pragma unroll
            for (int k = 0; k < 3; ++k)
                w2r[co][ci][k] = W2[(co*3 + ci)*3 + k];
            wdr[co][ci] = Wd[co*3 + ci];
        }
    }

    float2 acc[3];
    #pragma unroll
    for (int co = 0; co < 3; ++co) {
        float b = b2[co] + bd[co];
        acc[co] = make_float2(b, b);
    }

    const float2 z = make_float2(0.f, 0.f);
    #pragma unroll
    for (int ci = 0; ci < 3; ++ci) {
        float2 tm = (x4 > 0)      ? t[ci*NSP + i - 1] : z;
        float2 t0 =                 t[ci*NSP + i];
        float2 tp = (x4 < D4 - 1) ? t[ci*NSP + i + 1] : z;
        float2 ov =                 op[ci*NSP + i];
        #pragma unroll
        for (int co = 0; co < 3; ++co) {
            float2 a = acc[co];
            a = ffma2(tm, make_float2(w2r[co][ci][0], w2r[co][ci][0]), a);
            a = ffma2(t0, make_float2(w2r[co][ci][1], w2r[co][ci][1]), a);
            a = ffma2(tp, make_float2(w2r[co][ci][2], w2r[co][ci][2]), a);
            a = ffma2(ov, make_float2(wdr[co][ci],    wdr[co][ci]),    a);
            acc[co] = a;
        }
    }

    if (final_layer) {
        #pragma unroll
        for (int co = 0; co < 3; ++co) {
            ofinal[co*NSP + i]      = acc[co].x;
            ofinal[CN + co*NSP + i] = acc[co].y;
        }
    } else {
        #pragma unroll
        for (int co = 0; co < 3; ++co)
            onew[co*NSP + i] = acc[co];
    }
}

// ---------------------------------------------------------------------------
// Driver
// ---------------------------------------------------------------------------
extern "C" void kernel_launch(void* const* d_in, const int* in_sizes, int n_in,
                              void* d_out, int out_size)
{
    const float* f   = (const float*)d_in[0];
    const float* bnd = (const float*)d_in[1];
    const float* Wg  = (const float*)d_in[2];
    const float* bg  = (const float*)d_in[3];
    const float* W1  = (const float*)d_in[4];
    const float* b1  = (const float*)d_in[5];
    const float* W2  = (const float*)d_in[6];
    const float* b2  = (const float*)d_in[7];
    const float* Wd  = (const float*)d_in[8];
    const float* bd  = (const float*)d_in[9];

    static bool attr_done = false;
    if (!attr_done) {
        cudaFuncSetAttribute(wg_kernel,
            cudaFuncAttributeMaxDynamicSharedMemorySize, WG_SMEM);
        cudaFuncSetAttribute(w1_kernel,
            cudaFuncAttributeMaxDynamicSharedMemorySize, W1_SMEM);
        attr_done = true;
    }

    float2 *fi, *bi, *gg, *tt, *oA, *oB, *ub;
    float *wtf;
    cudaGetSymbolAddress((void**)&fi, s_fi);
    cudaGetSymbolAddress((void**)&bi, s_bi);
    cudaGetSymbolAddress((void**)&gg, s_g);
    cudaGetSymbolAddress((void**)&tt, s_t);
    cudaGetSymbolAddress((void**)&oA, s_oA);
    cudaGetSymbolAddress((void**)&oB, s_oB);
    cudaGetSymbolAddress((void**)&ub, s_u);
    cudaGetSymbolAddress((void**)&wtf, s_wgtf);

    pack_kernel<<<(CN/4 + 255) / 256, 256>>>(
        (const float4*)f, (const float4*)bnd, (float4*)fi, (float4*)bi,
        Wg, wtf);

    // boundary channels transformed once -> u[3..5]
    bx_kernel<<<dim3(NROW/64, 3), 256>>>(bi, ub + (size_t)3*NROW*32);

    dim3 cgrid(D1/2, D2/4, D3/8);
    const float2* cur = fi;
    float2* outs[LAYERS] = {oA, oB, oA, nullptr};

    for (int i = 0; i < LAYERS; ++i) {
        bx_kernel<<<dim3(NROW/64, 3), 256>>>(cur, ub);   // cur -> u[0..2]
        wg_kernel<<<cgrid, 256, WG_SMEM>>>(
            ub, wtf + i*3888, bg + i*3, gg);
        w1_kernel<<<cgrid, 256, W1_SMEM>>>(
            gg, W1 + i*243, b1 + i*3, tt);
        w2wd_kernel<<<(NSP + 255) / 256, 256>>>(
            tt, cur, W2 + i*27, b2 + i*3, Wd + i*9, bd + i*3,
            outs[i], (float*)d_out, (i == LAYERS - 1) ? 1 : 0);
        cur = outs[i];
    }
}

// round 11
// speedup vs baseline: 1.9331x; 1.9331x over previous
#include <cuda_runtime.h>
#include <cuda_bf16.h>

// ---------------------------------------------------------------------------
// Problem constants
// ---------------------------------------------------------------------------
#define LAYERS 4
#define NC 3
#define D1 48
#define D2 48
#define D3 48
#define D4 24
#define NROW (D1*D2*D3)           // 110,592 x4-rows per channel
#define NSP  (D1*D2*D3*D4)        // 2,654,208 spatial points per channel
#define CN   (NC*NSP)             // 7,962,624 elems per batch image

// Scratch: batch-interleaved tensors, float2 = {b0, b1}
__device__ float2 s_fi[CN];
__device__ float2 s_bi[CN];
__device__ float2 s_g [CN];
__device__ float2 s_t [CN];
__device__ float2 s_oA[CN];
__device__ float2 s_oB[CN];
// x4-Winograd-transformed inputs: [ci 0..5][row][group*8+point] f2
__device__ float2 s_u[6*(size_t)NROW*32];
// Winograd-transformed Wg weights, scalar: [L][ci][k123][co*8+p]
__device__ float s_wgtf[LAYERS*6*27*24];

// ---- packed f32x2 ops ------------------------------------------------------
__device__ __forceinline__ float2 ffma2(float2 a, float2 b, float2 c) {
    unsigned long long ua, ub, uc, ud;
    ua = *reinterpret_cast<const unsigned long long*>(&a);
    ub = *reinterpret_cast<const unsigned long long*>(&b);
    uc = *reinterpret_cast<const unsigned long long*>(&c);
    asm("fma.rn.f32x2 %0, %1, %2, %3;" : "=l"(ud) : "l"(ua), "l"(ub), "l"(uc));
    return *reinterpret_cast<float2*>(&ud);
}
__device__ __forceinline__ float2 fadd2(float2 a, float2 b) {
    unsigned long long ua, ub, ud;
    ua = *reinterpret_cast<const unsigned long long*>(&a);
    ub = *reinterpret_cast<const unsigned long long*>(&b);
    asm("add.rn.f32x2 %0, %1, %2;" : "=l"(ud) : "l"(ua), "l"(ub));
    return *reinterpret_cast<float2*>(&ud);
}
__device__ __forceinline__ float2 fsub2(float2 a, float2 b) {   // a - b
    return ffma2(b, make_float2(-1.f, -1.f), a);
}

// B^T (F(6,3), points {0,±1,±2,±1/2,inf}) — validated R8/R9
__device__ __forceinline__ void btrans8(const float2* x, float2* u) {
    const float2 z = make_float2(0.f, 0.f);
    u[0] = ffma2(fsub2(x[4], x[2]), make_float2(5.25f,5.25f), fsub2(x[0], x[6]));
    u[7] = ffma2(fsub2(x[3], x[5]), make_float2(5.25f,5.25f), fsub2(x[7], x[1]));
    {
        float2 e = ffma2(x[4], make_float2(-4.25f,-4.25f), fadd2(x[2], x[6]));
        float2 o = ffma2(x[3], make_float2(-4.25f,-4.25f), fadd2(x[1], x[5]));
        u[1] = fadd2(e, o);
        u[2] = fsub2(e, o);
    }
    {
        float2 e = ffma2(x[2], make_float2(0.25f,0.25f),
                   ffma2(x[4], make_float2(-1.25f,-1.25f), x[6]));
        float2 o = ffma2(x[1], make_float2(0.5f,0.5f),
                   ffma2(x[3], make_float2(-2.5f,-2.5f),
                   ffma2(x[5], make_float2(2.f,2.f), z)));
        u[3] = fadd2(e, o);
        u[4] = fsub2(e, o);
    }
    {
        float2 e = ffma2(x[2], make_float2(4.f,4.f),
                   ffma2(x[4], make_float2(-5.f,-5.f), x[6]));
        float2 o = ffma2(x[1], make_float2(2.f,2.f),
                   ffma2(x[3], make_float2(-2.5f,-2.5f),
                   ffma2(x[5], make_float2(0.5f,0.5f), z)));
        u[5] = fadd2(e, o);
        u[6] = fsub2(e, o);
    }
}

// ---------------------------------------------------------------------------
// Pack (+ folded Wg weight transform)
// ---------------------------------------------------------------------------
__global__ void pack_kernel(const float4* __restrict__ f,
                            const float4* __restrict__ bnd,
                            float4* __restrict__ fi,
                            float4* __restrict__ bi,
                            const float* __restrict__ Wg,
                            float* __restrict__ wtf) {
    int i = blockIdx.x * blockDim.x + threadIdx.x;
    if (i < LAYERS*6*27*3) {
        int co = i % 3;  int r = i / 3;
        int k123 = r % 27; r /= 27;
        int ci = r % 6;    int L = r / 6;
        const float* w = Wg + L*1458 + (co*6 + ci)*81 + k123*3;
        float w0 = w[0], w1 = w[1], w2 = w[2];
        float p[8];
        p[0] = w0;
        p[1] = (-2.f/9.f)  * (w0 + w1 + w2);
        p[2] = (-2.f/9.f)  * (w0 - w1 + w2);
        p[3] = (1.f/90.f)*w0 + (1.f/45.f)*w1 + (2.f/45.f)*w2;
        p[4] = (1.f/90.f)*w0 - (1.f/45.f)*w1 + (2.f/45.f)*w2;
        p[5] = (32.f/45.f)*w0 + (16.f/45.f)*w1 + (8.f/45.f)*w2;
        p[6] = (32.f/45.f)*w0 - (16.f/45.f)*w1 + (8.f/45.f)*w2;
        p[7] = w2;
        float* o = wtf + ((L*6 + ci)*27 + k123)*24 + co*8;
        #pragma unroll
        for (int m = 0; m < 8; ++m) o[m] = p[m];
    }
    if (i >= CN / 4) return;
    float4 a = f[i],   b = f[i + CN / 4];
    fi[2*i]     = make_float4(a.x, b.x, a.y, b.y);
    fi[2*i + 1] = make_float4(a.z, b.z, a.w, b.w);
    a = bnd[i]; b = bnd[i + CN / 4];
    bi[2*i]     = make_float4(a.x, b.x, a.y, b.y);
    bi[2*i + 1] = make_float4(a.z, b.z, a.w, b.w);
}

// ---------------------------------------------------------------------------
// x4 input transform, global -> global (used once for f, once for boundary)
// [UNCHANGED — R9 passing]
// ---------------------------------------------------------------------------
__global__ __launch_bounds__(256) void bx_kernel(
    const float2* __restrict__ src, float2* __restrict__ dst)
{
    __shared__ float4 sraw[64*13];
    const int ch   = blockIdx.y;
    const int row0 = blockIdx.x * 64;
    const float4* s = (const float4*)(src + (size_t)ch*NSP + (size_t)row0*D4);
    for (int idx = threadIdx.x; idx < 768; idx += 256) {
        int r = idx / 12, c = idx % 12;
        sraw[r*13 + c] = s[idx];
    }
    __syncthreads();

    const int r = threadIdx.x >> 2, g = threadIdx.x & 3;
    const float2* rp = (const float2*)&sraw[r*13];
    const float2 z = make_float2(0.f, 0.f);
    float2 x[8];
    #pragma unroll
    for (int e = 0; e < 8; ++e) {
        int x4 = 6*g - 1 + e;
        x[e] = ((unsigned)x4 < (unsigned)D4) ? rp[x4] : z;
    }
    float2 u[8];
    btrans8(x, u);
    float4* d = (float4*)(dst + ((size_t)(ch*NROW + row0 + r))*32) + g*4;
    #pragma unroll
    for (int m = 0; m < 4; ++m)
        d[m] = make_float4(u[2*m].x, u[2*m].y, u[2*m+1].x, u[2*m+1].y);
}

// ---------------------------------------------------------------------------
// Wg conv in Winograd(x4) domain.  [EXACT R9 VERSION — 333 us measured]
// ---------------------------------------------------------------------------
#define WG_SMEM (240*17*16 + 648*4)   // 67872 B

__global__ __launch_bounds__(256, 2) void wg_kernel(
    const float2* __restrict__ ubuf,
    const float*  __restrict__ wgt,
    const float*  __restrict__ bias,
    float2* __restrict__ out)
{
    extern __shared__ float4 dsm4[];
    float4* sIn = dsm4;                       // [240][17]
    float*  sWf = (float*)(dsm4 + 240*17);    // [27][24]

    const int tid = threadIdx.x;
    const int x3l = tid & 7;
    const int q   = (tid >> 3) & 3;
    const int x2l = (tid >> 5) & 3;
    const int x1l = tid >> 7;
    const int x1g = blockIdx.x * 2;
    const int x2g = blockIdx.y * 4;
    const int x3g = blockIdx.z * 8;

    float2 acc[3][8];
    #pragma unroll
    for (int co = 0; co < 3; ++co)
        #pragma unroll
        for (int m = 0; m < 8; ++m) acc[co][m] = make_float2(0.f, 0.f);

    for (int ci = 0; ci < 6; ++ci) {
        const float4* __restrict__ usrc =
            (const float4*)(ubuf + (size_t)ci*NROW*32);
        __syncthreads();
        {
            const float4* wsrc = (const float4*)(wgt + ci*648);
            for (int s = tid; s < 162; s += 256)
                ((float4*)sWf)[s] = wsrc[s];
        }
        for (int idx = tid; idx < 240*16; idx += 256) {
            int r = idx >> 4, c = idx & 15;
            int p3 = r % 10; int t = r / 10; int p2 = t % 6; int p1 = t / 6;
            int g1 = x1g - 1 + p1, g2 = x2g - 1 + p2, g3 = x3g - 1 + p3;
            float4 v = make_float4(0.f, 0.f, 0.f, 0.f);
            if ((unsigned)g1 < (unsigned)D1 && (unsigned)g2 < (unsigned)D2 &&
                (unsigned)g3 < (unsigned)D3)
                v = usrc[(size_t)((g1*D2 + g2)*D3 + g3)*16 + c];
            sIn[r*17 + c] = v;
        }
        __syncthreads();

        #pragma unroll 1
        for (int k1 = 0; k1 < 3; ++k1) {
            #pragma unroll
            for (int k23 = 0; k23 < 9; ++k23) {
                const int k2 = k23 / 3, k3 = k23 % 3;
                const float4* up = sIn
                    + (((x1l + k1)*6 + (x2l + k2))*10 + (x3l + k3))*17 + q*4;
                float4 ua[4];
                #pragma unroll
                for (int m = 0; m < 4; ++m) ua[m] = up[m];
                const float2* uf = reinterpret_cast<const float2*>(ua);

                const float4* wp = (const float4*)(sWf + (k1*9 + k23)*24);
                #pragma unroll
                for (int co = 0; co < 3; ++co) {
                    float4 wa = wp[co*2];
                    float4 wb = wp[co*2 + 1];
                    acc[co][0] = ffma2(uf[0], make_float2(wa.x,wa.x), acc[co][0]);
                    acc[co][1] = ffma2(uf[1], make_float2(wa.y,wa.y), acc[co][1]);
                    acc[co][2] = ffma2(uf[2], make_float2(wa.z,wa.z), acc[co][2]);
                    acc[co][3] = ffma2(uf[3], make_float2(wa.w,wa.w), acc[co][3]);
                    acc[co][4] = ffma2(uf[4], make_float2(wb.x,wb.x), acc[co][4]);
                    acc[co][5] = ffma2(uf[5], make_float2(wb.y,wb.y), acc[co][5]);
                    acc[co][6] = ffma2(uf[6], make_float2(wb.z,wb.z), acc[co][6]);
                    acc[co][7] = ffma2(uf[7], make_float2(wb.w,wb.w), acc[co][7]);
                }
            }
        }
    }

    const int x1 = x1g + x1l, x2 = x2g + x2l, x3 = x3g + x3l;
    const int base = ((x1*D2 + x2)*D3 + x3)*D4 + q*6;
    #pragma unroll
    for (int co = 0; co < 3; ++co) {
        float bsc = __ldg(bias + co);
        float2 bb = make_float2(bsc, bsc);
        float2* m = acc[co];
        float2 s1 = fadd2(m[1], m[2]), d1 = fsub2(m[1], m[2]);
        float2 s3 = fadd2(m[3], m[4]), d3 = fsub2(m[3], m[4]);
        float2 s5 = fadd2(m[5], m[6]), d5 = fsub2(m[5], m[6]);
        float2 y[6];
        y[0] = fadd2(fadd2(fadd2(m[0], s1), fadd2(s3, s5)), bb);
        y[1] = ffma2(d3, make_float2(2.f,2.f),
               ffma2(d5, make_float2(0.5f,0.5f), fadd2(d1, bb)));
        y[2] = ffma2(s3, make_float2(4.f,4.f),
               ffma2(s5, make_float2(0.25f,0.25f), fadd2(s1, bb)));
        y[3] = ffma2(d3, make_float2(8.f,8.f),
               ffma2(d5, make_float2(0.125f,0.125f), fadd2(d1, bb)));
        y[4] = ffma2(s3, make_float2(16.f,16.f),
               ffma2(s5, make_float2(0.0625f,0.0625f), fadd2(s1, bb)));
        y[5] = ffma2(d3, make_float2(32.f,32.f),
               ffma2(d5, make_float2(0.03125f,0.03125f),
               fadd2(fadd2(d1, m[7]), bb)));
        float4* op = (float4*)(out + co*NSP + base);
        #pragma unroll
        for (int j2 = 0; j2 < 3; ++j2)
            op[j2] = make_float4(y[2*j2].x, y[2*j2].y,
                                 y[2*j2+1].x, y[2*j2+1].y);
    }
}

// ---------------------------------------------------------------------------
// W1 conv  [UNCHANGED — R7/R9 passing]
// ---------------------------------------------------------------------------
#define W1_W_F2     (81*4)
#define W1_STAGE_F2 (240*26)
#define W1_SMEM     ((W1_W_F2 + W1_STAGE_F2)*8)

__global__ __launch_bounds__(256, 3) void w1_kernel(
    const float2* __restrict__ g,
    const float*  __restrict__ W,  const float* __restrict__ bias,
    float2* __restrict__ out)
{
    extern __shared__ float2 dsm[];
    float2* sW  = dsm;
    float2* sIn = dsm + W1_W_F2;

    const int tid = threadIdx.x;
    const int x3l = tid & 7;
    const int q   = (tid >> 3) & 3;
    const int x2l = (tid >> 5) & 3;
    const int x1l = tid >> 7;
    const int x1g = blockIdx.x * 2;
    const int x2g = blockIdx.y * 4;
    const int x3g = blockIdx.z * 8;

    for (int s = tid; s < 81*3; s += 256) {
        int grp = s / 3, co = s % 3;
        int ci = grp / 27, k = grp % 27;
        float w = W[(co*3 + ci)*27 + k];
        sW[grp*4 + co] = make_float2(w, w);
    }

    float2 acc[3][6];
    #pragma unroll
    for (int co = 0; co < 3; ++co) {
        float b = __ldg(bias + co);
        #pragma unroll
        for (int j = 0; j < 6; ++j) acc[co][j] = make_float2(b, b);
    }

    for (int ci = 0; ci < 3; ++ci) {
        const float2* __restrict__ src = g + ci * NSP;
        __syncthreads();
        for (int idx = tid; idx < 240*12; idx += 256) {
            int row = idx / 12, c = idx % 12;
            int p3 = row % 10; int t = row / 10; int p2 = t % 6; int p1 = t / 6;
            int g1 = x1g - 1 + p1, g2 = x2g - 1 + p2, g3 = x3g - 1 + p3;
            float4 v = make_float4(0.f, 0.f, 0.f, 0.f);
            if ((unsigned)g1 < (unsigned)D1 && (unsigned)g2 < (unsigned)D2 &&
                (unsigned)g3 < (unsigned)D3)
                v = ((const float4*)src)[((g1*D2 + g2)*D3 + g3)*12 + c];
            ((float4*)sIn)[row*13 + c] = v;
        }
        __syncthreads();

        const float2* wci = sW + ci * 108;
        #pragma unroll 1
        for (int k1 = 0; k1 < 3; ++k1) {
            #pragma unroll
            for (int k23 = 0; k23 < 9; ++k23) {
                const int k2 = k23 / 3, k3 = k23 % 3;
                const float4* ip = (const float4*)sIn
                    + (((x1l + k1)*6 + (x2l + k2))*10 + (x3l + k3))*13 + q*3;
                float4 a4[3];
                #pragma unroll
                for (int m = 0; m < 3; ++m) a4[m] = ip[m];
                const float2* uf = reinterpret_cast<const float2*>(a4);

                const float2* wp = wci + (k1*9 + k23)*4;
                float2 w0 = wp[0];
                float2 w1 = wp[1];
                float2 w2 = wp[2];
                #pragma unroll
                for (int j = 0; j < 6; ++j) {
                    acc[0][j] = ffma2(uf[j], w0, acc[0][j]);
                    acc[1][j] = ffma2(uf[j], w1, acc[1][j]);
                    acc[2][j] = ffma2(uf[j], w2, acc[2][j]);
                }
            }
        }
    }

    const int x1 = x1g + x1l, x2 = x2g + x2l, x3 = x3g + x3l;
    const int base = ((x1*D2 + x2)*D3 + x3)*D4 + q*6;
    #pragma unroll
    for (int co = 0; co < 3; ++co) {
        float4* op = (float4*)(out + co*NSP + base);
        #pragma unroll
        for (int j2 = 0; j2 < 3; ++j2)
            op[j2] = make_float4(acc[co][2*j2].x,   acc[co][2*j2].y,
                                 acc[co][2*j2+1].x, acc[co][2*j2+1].y);
    }
}

// ---------------------------------------------------------------------------
// Fused epilogue + x4 transform:
//   out = conv(t, W2, pad x4 1) + b2 + conv(cur, Wd) + bd        (w2wd math, R1+)
//   non-final: write out AND its B^T x4-transform (replaces per-layer bx)
//   final:     write de-interleaved result to ofinal
// Block = 64 rows; thread = (row r, group g of 6 x4-outputs).
// ---------------------------------------------------------------------------
__global__ __launch_bounds__(256) void w2t_kernel(
    const float2* __restrict__ t,  const float2* __restrict__ cur,
    const float*  __restrict__ W2, const float* __restrict__ b2,
    const float*  __restrict__ Wd, const float* __restrict__ bd,
    float2* __restrict__ onew, float2* __restrict__ ubuf,
    float* __restrict__ ofinal, int final_layer)
{
    __shared__ float4 sT[3][64][13];    // t stage; later reused for out rows
    __shared__ float  sw[40];           // [0:27) W2, [27:36) Wd, [36:39) b2+bd

    const int tid  = threadIdx.x;
    const int row0 = blockIdx.x * 64;
    const float2 z = make_float2(0.f, 0.f);

    if (tid < 27) sw[tid] = W2[tid];
    else if (tid < 36) sw[tid] = Wd[tid - 27];
    else if (tid < 39) sw[tid] = b2[tid - 36] + bd[tid - 36];

    // stage t rows (zero the pad f4 col 12 -> f2 cols 24,25 read as 0)
    for (int idx = tid; idx < 3*64*13; idx += 256) {
        int c = idx % 13; int rr = idx / 13;
        int r = rr % 64, ch = rr / 64;
        float4 v = make_float4(0.f, 0.f, 0.f, 0.f);
        if (c < 12)
            v = ((const float4*)(t + (size_t)ch*NSP))[(size_t)(row0 + r)*12 + c];
        sT[ch][r][c] = v;
    }
    __syncthreads();

    const int r = tid >> 2, g = tid & 3;

    float2 r12[3][6];
    #pragma unroll
    for (int co = 0; co < 3; ++co) {
        float bs = sw[36 + co];
        #pragma unroll
        for (int j = 0; j < 6; ++j) r12[co][j] = make_float2(bs, bs);
    }

    #pragma unroll
    for (int ci = 0; ci < 3; ++ci) {
        const float2* tr = (const float2*)&sT[ci][r][0];
        float2 tv[8];
        #pragma unroll
        for (int e = 0; e < 8; ++e) {
            int col = g*6 - 1 + e;
            tv[e] = (col >= 0) ? tr[col] : z;    // col<=24; 24/25 zero pad
        }
        const float4* cp = (const float4*)(cur + (size_t)ci*NSP)
                           + (size_t)(row0 + r)*12 + g*3;
        float4 c4[3];
        #pragma unroll
        for (int m = 0; m < 3; ++m) c4[m] = cp[m];
        const float2* cf = reinterpret_cast<const float2*>(c4);

        #pragma unroll
        for (int co = 0; co < 3; ++co) {
            float w0 = sw[(co*3 + ci)*3 + 0];
            float w1 = sw[(co*3 + ci)*3 + 1];
            float w2 = sw[(co*3 + ci)*3 + 2];
            float wd = sw[27 + co*3 + ci];
            #pragma unroll
            for (int j = 0; j < 6; ++j) {
                float2 a = r12[co][j];
                a = ffma2(tv[j],     make_float2(w0, w0), a);
                a = ffma2(tv[j + 1], make_float2(w1, w1), a);
                a = ffma2(tv[j + 2], make_float2(w2, w2), a);
                a = ffma2(cf[j],     make_float2(wd, wd), a);
                r12[co][j] = a;
            }
        }
    }

    if (final_layer) {
        // de-interleave to (B, C, ...) fp32 output
        #pragma unroll
        for (int co = 0; co < 3; ++co) {
            size_t base = (size_t)co*NSP + (size_t)(row0 + r)*24 + g*6;
            float2* o0 = (float2*)(ofinal + base);
            float2* o1 = (float2*)(ofinal + CN + base);
            #pragma unroll
            for (int m = 0; m < 3; ++m) {
                o0[m] = make_float2(r12[co][2*m].x, r12[co][2*m + 1].x);
                o1[m] = make_float2(r12[co][2*m].y, r12[co][2*m + 1].y);
            }
        }
        return;
    }

    // write layer output (interleaved) to global
    {
        size_t base = (size_t)(row0 + r)*12 + g*3;   // f4 units
        #pragma unroll
        for (int co = 0; co < 3; ++co) {
            float4* op = (float4*)(onew + (size_t)co*NSP) + base;
            #pragma unroll
            for (int m = 0; m < 3; ++m)
                op[m] = make_float4(r12[co][2*m].x,   r12[co][2*m].y,
                                    r12[co][2*m+1].x, r12[co][2*m+1].y);
        }
    }

    // reuse sT for out rows, then transform (B^T) and write u
    __syncthreads();           // all phase-2 sT reads complete
    {
        float2* dr;
        #pragma unroll
        for (int co = 0; co < 3; ++co) {
            dr = (float2*)&sT[co][r][0];
            #pragma unroll
            for (int j = 0; j < 6; ++j) dr[g*6 + j] = r12[co][j];
            if (g == 3) dr[24] = z;    // zero pad col (read by e=7 of g=3)
        }
    }
    __syncthreads();

    #pragma unroll
    for (int ch = 0; ch < 3; ++ch) {
        const float2* rp = (const float2*)&sT[ch][r][0];
        float2 x[8];
        #pragma unroll
        for (int e = 0; e < 8; ++e) {
            int x4 = 6*g - 1 + e;
            x[e] = (x4 >= 0) ? rp[x4] : z;       // x4 == 24 reads zeroed pad
        }
        float2 u[8];
        btrans8(x, u);
        float4* d = (float4*)(ubuf + ((size_t)(ch*NROW + row0 + r))*32) + g*4;
        #pragma unroll
        for (int m = 0; m < 4; ++m)
            d[m] = make_float4(u[2*m].x, u[2*m].y, u[2*m+1].x, u[2*m+1].y);
    }
}

// ---------------------------------------------------------------------------
// Driver
// ---------------------------------------------------------------------------
extern "C" void kernel_launch(void* const* d_in, const int* in_sizes, int n_in,
                              void* d_out, int out_size)
{
    const float* f   = (const float*)d_in[0];
    const float* bnd = (const float*)d_in[1];
    const float* Wg  = (const float*)d_in[2];
    const float* bg  = (const float*)d_in[3];
    const float* W1  = (const float*)d_in[4];
    const float* b1  = (const float*)d_in[5];
    const float* W2  = (const float*)d_in[6];
    const float* b2  = (const float*)d_in[7];
    const float* Wd  = (const float*)d_in[8];
    const float* bd  = (const float*)d_in[9];

    static bool attr_done = false;
    if (!attr_done) {
        cudaFuncSetAttribute(wg_kernel,
            cudaFuncAttributeMaxDynamicSharedMemorySize, WG_SMEM);
        cudaFuncSetAttribute(w1_kernel,
            cudaFuncAttributeMaxDynamicSharedMemorySize, W1_SMEM);
        attr_done = true;
    }

    float2 *fi, *bi, *gg, *tt, *oA, *oB, *ub;
    float *wtf;
    cudaGetSymbolAddress((void**)&fi, s_fi);
    cudaGetSymbolAddress((void**)&bi, s_bi);
    cudaGetSymbolAddress((void**)&gg, s_g);
    cudaGetSymbolAddress((void**)&tt, s_t);
    cudaGetSymbolAddress((void**)&oA, s_oA);
    cudaGetSymbolAddress((void**)&oB, s_oB);
    cudaGetSymbolAddress((void**)&ub, s_u);
    cudaGetSymbolAddress((void**)&wtf, s_wgtf);

    pack_kernel<<<(CN/4 + 255) / 256, 256>>>(
        (const float4*)f, (const float4*)bnd, (float4*)fi, (float4*)bi,
        Wg, wtf);

    // transforms done once: f -> u[0..2] (layer 0), boundary -> u[3..5]
    bx_kernel<<<dim3(NROW/64, 3), 256>>>(fi, ub);
    bx_kernel<<<dim3(NROW/64, 3), 256>>>(bi, ub + (size_t)3*NROW*32);
    // launch order: harness(2) + pack + 2x bx => first wg in ncu -s 5 slot

    dim3 cgrid(D1/2, D2/4, D3/8);
    const float2* cur = fi;
    float2* outs[LAYERS] = {oA, oB, oA, nullptr};

    for (int i = 0; i < LAYERS; ++i) {
        wg_kernel<<<cgrid, 256, WG_SMEM>>>(
            ub, wtf + i*3888, bg + i*3, gg);
        w1_kernel<<<cgrid, 256, W1_SMEM>>>(
            gg, W1 + i*243, b1 + i*3, tt);
        // epilogue + transform for next layer's wg input
        w2t_kernel<<<NROW/64, 256>>>(
            tt, cur, W2 + i*27, b2 + i*3, Wd + i*9, bd + i*3,
            outs[i], ub, (float*)d_out, (i == LAYERS - 1) ? 1 : 0);
        cur = outs[i];
    }
}

// round 12
// speedup vs baseline: 2.0255x; 1.0478x over previous
#include <cuda_runtime.h>
#include <cuda_bf16.h>

// ---------------------------------------------------------------------------
// Problem constants
// ---------------------------------------------------------------------------
#define LAYERS 4
#define NC 3
#define D1 48
#define D2 48
#define D3 48
#define D4 24
#define NROW (D1*D2*D3)           // 110,592 x4-rows per channel
#define NSP  (D1*D2*D3*D4)        // 2,654,208 spatial points per channel
#define CN   (NC*NSP)             // 7,962,624 elems per batch image

// Scratch: batch-interleaved tensors, float2 = {b0, b1}
__device__ float2 s_fi[CN];
__device__ float2 s_bi[CN];
__device__ float2 s_g [CN];
__device__ float2 s_t [CN];
__device__ float2 s_oA[CN];
__device__ float2 s_oB[CN];
// x4-Winograd-transformed inputs: [ci 0..5][row][group*8+point] f2
__device__ float2 s_u[6*(size_t)NROW*32];
// Winograd-transformed Wg weights, scalar: [L][ci][k123][co*8+p]
__device__ float s_wgtf[LAYERS*6*27*24];

// ---- packed f32x2 ops ------------------------------------------------------
__device__ __forceinline__ float2 ffma2(float2 a, float2 b, float2 c) {
    unsigned long long ua, ub, uc, ud;
    ua = *reinterpret_cast<const unsigned long long*>(&a);
    ub = *reinterpret_cast<const unsigned long long*>(&b);
    uc = *reinterpret_cast<const unsigned long long*>(&c);
    asm("fma.rn.f32x2 %0, %1, %2, %3;" : "=l"(ud) : "l"(ua), "l"(ub), "l"(uc));
    return *reinterpret_cast<float2*>(&ud);
}
__device__ __forceinline__ float2 fadd2(float2 a, float2 b) {
    unsigned long long ua, ub, ud;
    ua = *reinterpret_cast<const unsigned long long*>(&a);
    ub = *reinterpret_cast<const unsigned long long*>(&b);
    asm("add.rn.f32x2 %0, %1, %2;" : "=l"(ud) : "l"(ua), "l"(ub));
    return *reinterpret_cast<float2*>(&ud);
}
__device__ __forceinline__ float2 fsub2(float2 a, float2 b) {   // a - b
    return ffma2(b, make_float2(-1.f, -1.f), a);
}
__device__ __forceinline__ void cp_async16(void* smem, const void* gmem) {
    unsigned sa = (unsigned)__cvta_generic_to_shared(smem);
    asm volatile("cp.async.cg.shared.global [%0], [%1], 16;"
                 :: "r"(sa), "l"(gmem) : "memory");
}

// B^T (F(6,3), points {0,±1,±2,±1/2,inf}) — validated R8/R9
__device__ __forceinline__ void btrans8(const float2* x, float2* u) {
    const float2 z = make_float2(0.f, 0.f);
    u[0] = ffma2(fsub2(x[4], x[2]), make_float2(5.25f,5.25f), fsub2(x[0], x[6]));
    u[7] = ffma2(fsub2(x[3], x[5]), make_float2(5.25f,5.25f), fsub2(x[7], x[1]));
    {
        float2 e = ffma2(x[4], make_float2(-4.25f,-4.25f), fadd2(x[2], x[6]));
        float2 o = ffma2(x[3], make_float2(-4.25f,-4.25f), fadd2(x[1], x[5]));
        u[1] = fadd2(e, o);
        u[2] = fsub2(e, o);
    }
    {
        float2 e = ffma2(x[2], make_float2(0.25f,0.25f),
                   ffma2(x[4], make_float2(-1.25f,-1.25f), x[6]));
        float2 o = ffma2(x[1], make_float2(0.5f,0.5f),
                   ffma2(x[3], make_float2(-2.5f,-2.5f),
                   ffma2(x[5], make_float2(2.f,2.f), z)));
        u[3] = fadd2(e, o);
        u[4] = fsub2(e, o);
    }
    {
        float2 e = ffma2(x[2], make_float2(4.f,4.f),
                   ffma2(x[4], make_float2(-5.f,-5.f), x[6]));
        float2 o = ffma2(x[1], make_float2(2.f,2.f),
                   ffma2(x[3], make_float2(-2.5f,-2.5f),
                   ffma2(x[5], make_float2(0.5f,0.5f), z)));
        u[5] = fadd2(e, o);
        u[6] = fsub2(e, o);
    }
}

// ---------------------------------------------------------------------------
// Pack (+ folded Wg weight transform)   [UNCHANGED — R9 passing]
// ---------------------------------------------------------------------------
__global__ void pack_kernel(const float4* __restrict__ f,
                            const float4* __restrict__ bnd,
                            float4* __restrict__ fi,
                            float4* __restrict__ bi,
                            const float* __restrict__ Wg,
                            float* __restrict__ wtf) {
    int i = blockIdx.x * blockDim.x + threadIdx.x;
    if (i < LAYERS*6*27*3) {
        int co = i % 3;  int r = i / 3;
        int k123 = r % 27; r /= 27;
        int ci = r % 6;    int L = r / 6;
        const float* w = Wg + L*1458 + (co*6 + ci)*81 + k123*3;
        float w0 = w[0], w1 = w[1], w2 = w[2];
        float p[8];
        p[0] = w0;
        p[1] = (-2.f/9.f)  * (w0 + w1 + w2);
        p[2] = (-2.f/9.f)  * (w0 - w1 + w2);
        p[3] = (1.f/90.f)*w0 + (1.f/45.f)*w1 + (2.f/45.f)*w2;
        p[4] = (1.f/90.f)*w0 - (1.f/45.f)*w1 + (2.f/45.f)*w2;
        p[5] = (32.f/45.f)*w0 + (16.f/45.f)*w1 + (8.f/45.f)*w2;
        p[6] = (32.f/45.f)*w0 - (16.f/45.f)*w1 + (8.f/45.f)*w2;
        p[7] = w2;
        float* o = wtf + ((L*6 + ci)*27 + k123)*24 + co*8;
        #pragma unroll
        for (int m = 0; m < 8; ++m) o[m] = p[m];
    }
    if (i >= CN / 4) return;
    float4 a = f[i],   b = f[i + CN / 4];
    fi[2*i]     = make_float4(a.x, b.x, a.y, b.y);
    fi[2*i + 1] = make_float4(a.z, b.z, a.w, b.w);
    a = bnd[i]; b = bnd[i + CN / 4];
    bi[2*i]     = make_float4(a.x, b.x, a.y, b.y);
    bi[2*i + 1] = make_float4(a.z, b.z, a.w, b.w);
}

// ---------------------------------------------------------------------------
// x4 input transform, global -> global  [UNCHANGED — R9 passing]
// ---------------------------------------------------------------------------
__global__ __launch_bounds__(256) void bx_kernel(
    const float2* __restrict__ src, float2* __restrict__ dst)
{
    __shared__ float4 sraw[64*13];
    const int ch   = blockIdx.y;
    const int row0 = blockIdx.x * 64;
    const float4* s = (const float4*)(src + (size_t)ch*NSP + (size_t)row0*D4);
    for (int idx = threadIdx.x; idx < 768; idx += 256) {
        int r = idx / 12, c = idx % 12;
        sraw[r*13 + c] = s[idx];
    }
    __syncthreads();

    const int r = threadIdx.x >> 2, g = threadIdx.x & 3;
    const float2* rp = (const float2*)&sraw[r*13];
    const float2 z = make_float2(0.f, 0.f);
    float2 x[8];
    #pragma unroll
    for (int e = 0; e < 8; ++e) {
        int x4 = 6*g - 1 + e;
        x[e] = ((unsigned)x4 < (unsigned)D4) ? rp[x4] : z;
    }
    float2 u[8];
    btrans8(x, u);
    float4* d = (float4*)(dst + ((size_t)(ch*NROW + row0 + r))*32) + g*4;
    #pragma unroll
    for (int m = 0; m < 4; ++m)
        d[m] = make_float4(u[2*m].x, u[2*m].y, u[2*m+1].x, u[2*m+1].y);
}

// ---------------------------------------------------------------------------
// Wg conv in Winograd(x4) domain — 512 threads, 1 block/SM,
// double-buffered cp.async staging (overlap stage of ci+1 with compute of ci).
// Tile x1=2, x2=8, x3=8, x4=24. Stage [4][10][10] rows x 16 f4, stride 17.
// ---------------------------------------------------------------------------
#define WG_BUF_F4  (400*17)                            // 6800 f4 per buffer
#define WG_W_F4    162                                 // per-ci weights (f4)
#define WG_SMEM    ((2*WG_BUF_F4 + 2*WG_W_F4)*16)      // 222784 B

__global__ __launch_bounds__(512, 1) void wg_kernel(
    const float2* __restrict__ ubuf,
    const float*  __restrict__ wgt,
    const float*  __restrict__ bias,
    float2* __restrict__ out)
{
    extern __shared__ float4 dsm4[];
    float4* buf0  = dsm4;
    float4* buf1  = dsm4 + WG_BUF_F4;
    float4* wbuf0 = dsm4 + 2*WG_BUF_F4;
    float4* wbuf1 = dsm4 + 2*WG_BUF_F4 + WG_W_F4;

    const int tid = threadIdx.x;
    const int x3l = tid & 7;
    const int q   = (tid >> 3) & 3;
    const int x2l = (tid >> 5) & 7;
    const int x1l = tid >> 8;
    const int x1g = blockIdx.x * 2;
    const int x2g = blockIdx.y * 8;
    const int x3g = blockIdx.z * 8;

    // async stage of channel ci into buffer b
    auto stage = [&](int ci, float4* dst, float4* wdst) {
        const float4* usrc = (const float4*)(ubuf + (size_t)ci*NROW*32);
        for (int idx = tid; idx < 6400; idx += 512) {
            int r = idx >> 4, c = idx & 15;
            int p3 = r % 10; int t = r / 10; int p2 = t % 10; int p1 = t / 10;
            int g1 = x1g - 1 + p1, g2 = x2g - 1 + p2, g3 = x3g - 1 + p3;
            float4* d = dst + r*17 + c;
            if ((unsigned)g1 < (unsigned)D1 && (unsigned)g2 < (unsigned)D2 &&
                (unsigned)g3 < (unsigned)D3)
                cp_async16(d, usrc + (size_t)((g1*D2 + g2)*D3 + g3)*16 + c);
            else
                *d = make_float4(0.f, 0.f, 0.f, 0.f);
        }
        if (tid < 162)
            cp_async16(wdst + tid, (const float4*)(wgt + ci*648) + tid);
    };

    float2 acc[3][8];
    #pragma unroll
    for (int co = 0; co < 3; ++co)
        #pragma unroll
        for (int m = 0; m < 8; ++m) acc[co][m] = make_float2(0.f, 0.f);

    stage(0, buf0, wbuf0);
    asm volatile("cp.async.commit_group;" ::: "memory");

    for (int ci = 0; ci < 6; ++ci) {
        if (ci + 1 < 6) {
            stage(ci + 1, (ci & 1) ? buf0 : buf1, (ci & 1) ? wbuf0 : wbuf1);
            asm volatile("cp.async.commit_group;" ::: "memory");
            asm volatile("cp.async.wait_group 1;" ::: "memory");
        } else {
            asm volatile("cp.async.wait_group 0;" ::: "memory");
        }
        __syncthreads();

        const float4* sIn = (ci & 1) ? buf1 : buf0;
        const float*  sWf = (const float*)((ci & 1) ? wbuf1 : wbuf0);

        #pragma unroll 1
        for (int k1 = 0; k1 < 3; ++k1) {
            #pragma unroll
            for (int k23 = 0; k23 < 9; ++k23) {
                const int k2 = k23 / 3, k3 = k23 % 3;
                const float4* up = sIn
                    + (((x1l + k1)*10 + (x2l + k2))*10 + (x3l + k3))*17 + q*4;
                float4 ua[4];
                #pragma unroll
                for (int m = 0; m < 4; ++m) ua[m] = up[m];
                const float2* uf = reinterpret_cast<const float2*>(ua);

                const float4* wp = (const float4*)(sWf + (k1*9 + k23)*24);
                #pragma unroll
                for (int co = 0; co < 3; ++co) {
                    float4 wa = wp[co*2];
                    float4 wb = wp[co*2 + 1];
                    acc[co][0] = ffma2(uf[0], make_float2(wa.x,wa.x), acc[co][0]);
                    acc[co][1] = ffma2(uf[1], make_float2(wa.y,wa.y), acc[co][1]);
                    acc[co][2] = ffma2(uf[2], make_float2(wa.z,wa.z), acc[co][2]);
                    acc[co][3] = ffma2(uf[3], make_float2(wa.w,wa.w), acc[co][3]);
                    acc[co][4] = ffma2(uf[4], make_float2(wb.x,wb.x), acc[co][4]);
                    acc[co][5] = ffma2(uf[5], make_float2(wb.y,wb.y), acc[co][5]);
                    acc[co][6] = ffma2(uf[6], make_float2(wb.z,wb.z), acc[co][6]);
                    acc[co][7] = ffma2(uf[7], make_float2(wb.w,wb.w), acc[co][7]);
                }
            }
        }
        __syncthreads();   // protect buf[ci&1] before it is re-staged
    }

    // inverse transform A^T m + bias (validated R8/R9)
    const int x1 = x1g + x1l, x2 = x2g + x2l, x3 = x3g + x3l;
    const int base = ((x1*D2 + x2)*D3 + x3)*D4 + q*6;
    #pragma unroll
    for (int co = 0; co < 3; ++co) {
        float bsc = __ldg(bias + co);
        float2 bb = make_float2(bsc, bsc);
        float2* m = acc[co];
        float2 s1 = fadd2(m[1], m[2]), d1 = fsub2(m[1], m[2]);
        float2 s3 = fadd2(m[3], m[4]), d3 = fsub2(m[3], m[4]);
        float2 s5 = fadd2(m[5], m[6]), d5 = fsub2(m[5], m[6]);
        float2 y[6];
        y[0] = fadd2(fadd2(fadd2(m[0], s1), fadd2(s3, s5)), bb);
        y[1] = ffma2(d3, make_float2(2.f,2.f),
               ffma2(d5, make_float2(0.5f,0.5f), fadd2(d1, bb)));
        y[2] = ffma2(s3, make_float2(4.f,4.f),
               ffma2(s5, make_float2(0.25f,0.25f), fadd2(s1, bb)));
        y[3] = ffma2(d3, make_float2(8.f,8.f),
               ffma2(d5, make_float2(0.125f,0.125f), fadd2(d1, bb)));
        y[4] = ffma2(s3, make_float2(16.f,16.f),
               ffma2(s5, make_float2(0.0625f,0.0625f), fadd2(s1, bb)));
        y[5] = ffma2(d3, make_float2(32.f,32.f),
               ffma2(d5, make_float2(0.03125f,0.03125f),
               fadd2(fadd2(d1, m[7]), bb)));
        float4* op = (float4*)(out + co*NSP + base);
        #pragma unroll
        for (int j2 = 0; j2 < 3; ++j2)
            op[j2] = make_float4(y[2*j2].x, y[2*j2].y,
                                 y[2*j2+1].x, y[2*j2+1].y);
    }
}

// ---------------------------------------------------------------------------
// W1 conv  [UNCHANGED — R7/R9 passing]
// ---------------------------------------------------------------------------
#define W1_W_F2     (81*4)
#define W1_STAGE_F2 (240*26)
#define W1_SMEM     ((W1_W_F2 + W1_STAGE_F2)*8)

__global__ __launch_bounds__(256, 3) void w1_kernel(
    const float2* __restrict__ g,
    const float*  __restrict__ W,  const float* __restrict__ bias,
    float2* __restrict__ out)
{
    extern __shared__ float2 dsm[];
    float2* sW  = dsm;
    float2* sIn = dsm + W1_W_F2;

    const int tid = threadIdx.x;
    const int x3l = tid & 7;
    const int q   = (tid >> 3) & 3;
    const int x2l = (tid >> 5) & 3;
    const int x1l = tid >> 7;
    const int x1g = blockIdx.x * 2;
    const int x2g = blockIdx.y * 4;
    const int x3g = blockIdx.z * 8;

    for (int s = tid; s < 81*3; s += 256) {
        int grp = s / 3, co = s % 3;
        int ci = grp / 27, k = grp % 27;
        float w = W[(co*3 + ci)*27 + k];
        sW[grp*4 + co] = make_float2(w, w);
    }

    float2 acc[3][6];
    #pragma unroll
    for (int co = 0; co < 3; ++co) {
        float b = __ldg(bias + co);
        #pragma unroll
        for (int j = 0; j < 6; ++j) acc[co][j] = make_float2(b, b);
    }

    for (int ci = 0; ci < 3; ++ci) {
        const float2* __restrict__ src = g + ci * NSP;
        __syncthreads();
        for (int idx = tid; idx < 240*12; idx += 256) {
            int row = idx / 12, c = idx % 12;
            int p3 = row % 10; int t = row / 10; int p2 = t % 6; int p1 = t / 6;
            int g1 = x1g - 1 + p1, g2 = x2g - 1 + p2, g3 = x3g - 1 + p3;
            float4 v = make_float4(0.f, 0.f, 0.f, 0.f);
            if ((unsigned)g1 < (unsigned)D1 && (unsigned)g2 < (unsigned)D2 &&
                (unsigned)g3 < (unsigned)D3)
                v = ((const float4*)src)[((g1*D2 + g2)*D3 + g3)*12 + c];
            ((float4*)sIn)[row*13 + c] = v;
        }
        __syncthreads();

        const float2* wci = sW + ci * 108;
        #pragma unroll 1
        for (int k1 = 0; k1 < 3; ++k1) {
            #pragma unroll
            for (int k23 = 0; k23 < 9; ++k23) {
                const int k2 = k23 / 3, k3 = k23 % 3;
                const float4* ip = (const float4*)sIn
                    + (((x1l + k1)*6 + (x2l + k2))*10 + (x3l + k3))*13 + q*3;
                float4 a4[3];
                #pragma unroll
                for (int m = 0; m < 3; ++m) a4[m] = ip[m];
                const float2* uf = reinterpret_cast<const float2*>(a4);

                const float2* wp = wci + (k1*9 + k23)*4;
                float2 w0 = wp[0];
                float2 w1 = wp[1];
                float2 w2 = wp[2];
                #pragma unroll
                for (int j = 0; j < 6; ++j) {
                    acc[0][j] = ffma2(uf[j], w0, acc[0][j]);
                    acc[1][j] = ffma2(uf[j], w1, acc[1][j]);
                    acc[2][j] = ffma2(uf[j], w2, acc[2][j]);
                }
            }
        }
    }

    const int x1 = x1g + x1l, x2 = x2g + x2l, x3 = x3g + x3l;
    const int base = ((x1*D2 + x2)*D3 + x3)*D4 + q*6;
    #pragma unroll
    for (int co = 0; co < 3; ++co) {
        float4* op = (float4*)(out + co*NSP + base);
        #pragma unroll
        for (int j2 = 0; j2 < 3; ++j2)
            op[j2] = make_float4(acc[co][2*j2].x,   acc[co][2*j2].y,
                                 acc[co][2*j2+1].x, acc[co][2*j2+1].y);
    }
}

// ---------------------------------------------------------------------------
// Fused epilogue  [UNCHANGED — passing since R1]
// ---------------------------------------------------------------------------
__global__ void w2wd_kernel(
    const float2* __restrict__ t,  const float2* __restrict__ op,
    const float*  __restrict__ W2, const float* __restrict__ b2,
    const float*  __restrict__ Wd, const float* __restrict__ bd,
    float2* __restrict__ onew, float* __restrict__ ofinal, int final_layer)
{
    int i = blockIdx.x * blockDim.x + threadIdx.x;
    if (i >= NSP) return;
    int x4 = i % D4;

    float w2r[3][3][3], wdr[3][3];
    #pragma unroll
    for (int co = 0; co < 3; ++co) {
        #pragma unroll
        for (int ci = 0; ci < 3; ++ci) {
            #pragma unroll
            for (int k = 0; k < 3; ++k)
                w2r[co][ci][k] = W2[(co*3 + ci)*3 + k];
            wdr[co][ci] = Wd[co*3 + ci];
        }
    }

    float2 acc[3];
    #pragma unroll
    for (int co = 0; co < 3; ++co) {
        float b = b2[co] + bd[co];
        acc[co] = make_float2(b, b);
    }

    const float2 z = make_float2(0.f, 0.f);
    #pragma unroll
    for (int ci = 0; ci < 3; ++ci) {
        float2 tm = (x4 > 0)      ? t[ci*NSP + i - 1] : z;
        float2 t0 =                 t[ci*NSP + i];
        float2 tp = (x4 < D4 - 1) ? t[ci*NSP + i + 1] : z;
        float2 ov =                 op[ci*NSP + i];
        #pragma unroll
        for (int co = 0; co < 3; ++co) {
            float2 a = acc[co];
            a = ffma2(tm, make_float2(w2r[co][ci][0], w2r[co][ci][0]), a);
            a = ffma2(t0, make_float2(w2r[co][ci][1], w2r[co][ci][1]), a);
            a = ffma2(tp, make_float2(w2r[co][ci][2], w2r[co][ci][2]), a);
            a = ffma2(ov, make_float2(wdr[co][ci],    wdr[co][ci]),    a);
            acc[co] = a;
        }
    }

    if (final_layer) {
        #pragma unroll
        for (int co = 0; co < 3; ++co) {
            ofinal[co*NSP + i]      = acc[co].x;
            ofinal[CN + co*NSP + i] = acc[co].y;
        }
    } else {
        #pragma unroll
        for (int co = 0; co < 3; ++co)
            onew[co*NSP + i] = acc[co];
    }
}

// ---------------------------------------------------------------------------
// Driver
// ---------------------------------------------------------------------------
extern "C" void kernel_launch(void* const* d_in, const int* in_sizes, int n_in,
                              void* d_out, int out_size)
{
    const float* f   = (const float*)d_in[0];
    const float* bnd = (const float*)d_in[1];
    const float* Wg  = (const float*)d_in[2];
    const float* bg  = (const float*)d_in[3];
    const float* W1  = (const float*)d_in[4];
    const float* b1  = (const float*)d_in[5];
    const float* W2  = (const float*)d_in[6];
    const float* b2  = (const float*)d_in[7];
    const float* Wd  = (const float*)d_in[8];
    const float* bd  = (const float*)d_in[9];

    static bool attr_done = false;
    if (!attr_done) {
        cudaFuncSetAttribute(wg_kernel,
            cudaFuncAttributeMaxDynamicSharedMemorySize, WG_SMEM);
        cudaFuncSetAttribute(w1_kernel,
            cudaFuncAttributeMaxDynamicSharedMemorySize, W1_SMEM);
        attr_done = true;
    }

    float2 *fi, *bi, *gg, *tt, *oA, *oB, *ub;
    float *wtf;
    cudaGetSymbolAddress((void**)&fi, s_fi);
    cudaGetSymbolAddress((void**)&bi, s_bi);
    cudaGetSymbolAddress((void**)&gg, s_g);
    cudaGetSymbolAddress((void**)&tt, s_t);
    cudaGetSymbolAddress((void**)&oA, s_oA);
    cudaGetSymbolAddress((void**)&oB, s_oB);
    cudaGetSymbolAddress((void**)&ub, s_u);
    cudaGetSymbolAddress((void**)&wtf, s_wgtf);

    pack_kernel<<<(CN/4 + 255) / 256, 256>>>(
        (const float4*)f, (const float4*)bnd, (float4*)fi, (float4*)bi,
        Wg, wtf);

    // boundary channels transformed once -> u[3..5]
    bx_kernel<<<dim3(NROW/64, 3), 256>>>(bi, ub + (size_t)3*NROW*32);

    dim3 ggrid(D1/2, D2/8, D3/8);      // wg: 24 x 6 x 6 = 864 blocks
    dim3 cgrid(D1/2, D2/4, D3/8);      // w1
    const float2* cur = fi;
    float2* outs[LAYERS] = {oA, oB, oA, nullptr};

    for (int i = 0; i < LAYERS; ++i) {
        bx_kernel<<<dim3(NROW/64, 3), 256>>>(cur, ub);   // cur -> u[0..2]
        wg_kernel<<<ggrid, 512, WG_SMEM>>>(
            ub, wtf + i*3888, bg + i*3, gg);
        w1_kernel<<<cgrid, 256, W1_SMEM>>>(
            gg, W1 + i*243, b1 + i*3, tt);
        w2wd_kernel<<<(NSP + 255) / 256, 256>>>(
            tt, cur, W2 + i*27, b2 + i*3, Wd + i*9, bd + i*3,
            outs[i], (float*)d_out, (i == LAYERS - 1) ? 1 : 0);
        cur = outs[i];
    }
}

// round 13
// speedup vs baseline: 2.1317x; 1.0524x over previous
#include <cuda_runtime.h>
#include <cuda_bf16.h>

// ---------------------------------------------------------------------------
// Problem constants
// ---------------------------------------------------------------------------
#define LAYERS 4
#define NC 3
#define D1 48
#define D2 48
#define D3 48
#define D4 24
#define NROW (D1*D2*D3)           // 110,592 x4-rows per channel
#define NSP  (D1*D2*D3*D4)        // 2,654,208 spatial points per channel
#define CN   (NC*NSP)             // 7,962,624 elems per batch image

// Scratch: batch-interleaved tensors, float2 = {b0, b1}
__device__ float2 s_fi[CN];
__device__ float2 s_bi[CN];
__device__ float2 s_g [CN];
__device__ float2 s_t [CN];
__device__ float2 s_oA[CN];
__device__ float2 s_oB[CN];
// x4-Winograd-transformed inputs: [ci 0..5][row][group*8+point] f2
__device__ float2 s_u[6*(size_t)NROW*32];
// Winograd-transformed Wg weights, scalar: [L][ci][k123][co*8+p]
__device__ float s_wgtf[LAYERS*6*27*24];

// ---- packed f32x2 ops ------------------------------------------------------
__device__ __forceinline__ float2 ffma2(float2 a, float2 b, float2 c) {
    unsigned long long ua, ub, uc, ud;
    ua = *reinterpret_cast<const unsigned long long*>(&a);
    ub = *reinterpret_cast<const unsigned long long*>(&b);
    uc = *reinterpret_cast<const unsigned long long*>(&c);
    asm("fma.rn.f32x2 %0, %1, %2, %3;" : "=l"(ud) : "l"(ua), "l"(ub), "l"(uc));
    return *reinterpret_cast<float2*>(&ud);
}
__device__ __forceinline__ float2 fadd2(float2 a, float2 b) {
    unsigned long long ua, ub, ud;
    ua = *reinterpret_cast<const unsigned long long*>(&a);
    ub = *reinterpret_cast<const unsigned long long*>(&b);
    asm("add.rn.f32x2 %0, %1, %2;" : "=l"(ud) : "l"(ua), "l"(ub));
    return *reinterpret_cast<float2*>(&ud);
}
__device__ __forceinline__ float2 fsub2(float2 a, float2 b) {   // a - b
    return ffma2(b, make_float2(-1.f, -1.f), a);
}
__device__ __forceinline__ void cp_async16(void* smem, const void* gmem) {
    unsigned sa = (unsigned)__cvta_generic_to_shared(smem);
    asm volatile("cp.async.cg.shared.global [%0], [%1], 16;"
                 :: "r"(sa), "l"(gmem) : "memory");
}

// B^T (F(6,3), points {0,±1,±2,±1/2,inf}) — validated R8/R9
__device__ __forceinline__ void btrans8(const float2* x, float2* u) {
    const float2 z = make_float2(0.f, 0.f);
    u[0] = ffma2(fsub2(x[4], x[2]), make_float2(5.25f,5.25f), fsub2(x[0], x[6]));
    u[7] = ffma2(fsub2(x[3], x[5]), make_float2(5.25f,5.25f), fsub2(x[7], x[1]));
    {
        float2 e = ffma2(x[4], make_float2(-4.25f,-4.25f), fadd2(x[2], x[6]));
        float2 o = ffma2(x[3], make_float2(-4.25f,-4.25f), fadd2(x[1], x[5]));
        u[1] = fadd2(e, o);
        u[2] = fsub2(e, o);
    }
    {
        float2 e = ffma2(x[2], make_float2(0.25f,0.25f),
                   ffma2(x[4], make_float2(-1.25f,-1.25f), x[6]));
        float2 o = ffma2(x[1], make_float2(0.5f,0.5f),
                   ffma2(x[3], make_float2(-2.5f,-2.5f),
                   ffma2(x[5], make_float2(2.f,2.f), z)));
        u[3] = fadd2(e, o);
        u[4] = fsub2(e, o);
    }
    {
        float2 e = ffma2(x[2], make_float2(4.f,4.f),
                   ffma2(x[4], make_float2(-5.f,-5.f), x[6]));
        float2 o = ffma2(x[1], make_float2(2.f,2.f),
                   ffma2(x[3], make_float2(-2.5f,-2.5f),
                   ffma2(x[5], make_float2(0.5f,0.5f), z)));
        u[5] = fadd2(e, o);
        u[6] = fsub2(e, o);
    }
}

// ---------------------------------------------------------------------------
// Pack (+ folded Wg weight transform)   [UNCHANGED — R9 passing]
// ---------------------------------------------------------------------------
__global__ void pack_kernel(const float4* __restrict__ f,
                            const float4* __restrict__ bnd,
                            float4* __restrict__ fi,
                            float4* __restrict__ bi,
                            const float* __restrict__ Wg,
                            float* __restrict__ wtf) {
    int i = blockIdx.x * blockDim.x + threadIdx.x;
    if (i < LAYERS*6*27*3) {
        int co = i % 3;  int r = i / 3;
        int k123 = r % 27; r /= 27;
        int ci = r % 6;    int L = r / 6;
        const float* w = Wg + L*1458 + (co*6 + ci)*81 + k123*3;
        float w0 = w[0], w1 = w[1], w2 = w[2];
        float p[8];
        p[0] = w0;
        p[1] = (-2.f/9.f)  * (w0 + w1 + w2);
        p[2] = (-2.f/9.f)  * (w0 - w1 + w2);
        p[3] = (1.f/90.f)*w0 + (1.f/45.f)*w1 + (2.f/45.f)*w2;
        p[4] = (1.f/90.f)*w0 - (1.f/45.f)*w1 + (2.f/45.f)*w2;
        p[5] = (32.f/45.f)*w0 + (16.f/45.f)*w1 + (8.f/45.f)*w2;
        p[6] = (32.f/45.f)*w0 - (16.f/45.f)*w1 + (8.f/45.f)*w2;
        p[7] = w2;
        float* o = wtf + ((L*6 + ci)*27 + k123)*24 + co*8;
        #pragma unroll
        for (int m = 0; m < 8; ++m) o[m] = p[m];
    }
    if (i >= CN / 4) return;
    float4 a = f[i],   b = f[i + CN / 4];
    fi[2*i]     = make_float4(a.x, b.x, a.y, b.y);
    fi[2*i + 1] = make_float4(a.z, b.z, a.w, b.w);
    a = bnd[i]; b = bnd[i + CN / 4];
    bi[2*i]     = make_float4(a.x, b.x, a.y, b.y);
    bi[2*i + 1] = make_float4(a.z, b.z, a.w, b.w);
}

// ---------------------------------------------------------------------------
// x4 input transform, global -> global (once for f, once for boundary)
// [UNCHANGED — R9 passing]
// ---------------------------------------------------------------------------
__global__ __launch_bounds__(256) void bx_kernel(
    const float2* __restrict__ src, float2* __restrict__ dst)
{
    __shared__ float4 sraw[64*13];
    const int ch   = blockIdx.y;
    const int row0 = blockIdx.x * 64;
    const float4* s = (const float4*)(src + (size_t)ch*NSP + (size_t)row0*D4);
    for (int idx = threadIdx.x; idx < 768; idx += 256) {
        int r = idx / 12, c = idx % 12;
        sraw[r*13 + c] = s[idx];
    }
    __syncthreads();

    const int r = threadIdx.x >> 2, g = threadIdx.x & 3;
    const float2* rp = (const float2*)&sraw[r*13];
    const float2 z = make_float2(0.f, 0.f);
    float2 x[8];
    #pragma unroll
    for (int e = 0; e < 8; ++e) {
        int x4 = 6*g - 1 + e;
        x[e] = ((unsigned)x4 < (unsigned)D4) ? rp[x4] : z;
    }
    float2 u[8];
    btrans8(x, u);
    float4* d = (float4*)(dst + ((size_t)(ch*NROW + row0 + r))*32) + g*4;
    #pragma unroll
    for (int m = 0; m < 4; ++m)
        d[m] = make_float4(u[2*m].x, u[2*m].y, u[2*m+1].x, u[2*m+1].y);
}

// ---------------------------------------------------------------------------
// Wg conv in Winograd(x4) domain — 512 threads, 1 block/SM, cp.async
// double-buffered (R12 structure). Tile now x1=4, x2=4, x3=8 (stage 360 rows
// vs 400 -> -10 % staging volume). Stride 17 f4 (odd) conflict-free.
// ---------------------------------------------------------------------------
#define WG_BUF_F4  (360*17)                            // 6120 f4 per buffer
#define WG_W_F4    162                                 // per-ci weights (f4)
#define WG_SMEM    ((2*WG_BUF_F4 + 2*WG_W_F4)*16)      // 201024 B

__global__ __launch_bounds__(512, 1) void wg_kernel(
    const float2* __restrict__ ubuf,
    const float*  __restrict__ wgt,
    const float*  __restrict__ bias,
    float2* __restrict__ out)
{
    extern __shared__ float4 dsm4[];
    float4* buf0  = dsm4;
    float4* buf1  = dsm4 + WG_BUF_F4;
    float4* wbuf0 = dsm4 + 2*WG_BUF_F4;
    float4* wbuf1 = dsm4 + 2*WG_BUF_F4 + WG_W_F4;

    const int tid = threadIdx.x;
    const int x3l = tid & 7;
    const int q   = (tid >> 3) & 3;
    const int x2l = (tid >> 5) & 3;
    const int x1l = (tid >> 7) & 3;
    const int x1g = blockIdx.x * 4;
    const int x2g = blockIdx.y * 4;
    const int x3g = blockIdx.z * 8;

    // async stage of channel ci
    auto stage = [&](int ci, float4* dst, float4* wdst) {
        const float4* usrc = (const float4*)(ubuf + (size_t)ci*NROW*32);
        for (int idx = tid; idx < 360*16; idx += 512) {
            int r = idx >> 4, c = idx & 15;
            int p3 = r % 10; int t = r / 10; int p2 = t % 6; int p1 = t / 6;
            int g1 = x1g - 1 + p1, g2 = x2g - 1 + p2, g3 = x3g - 1 + p3;
            float4* d = dst + r*17 + c;
            if ((unsigned)g1 < (unsigned)D1 && (unsigned)g2 < (unsigned)D2 &&
                (unsigned)g3 < (unsigned)D3)
                cp_async16(d, usrc + (size_t)((g1*D2 + g2)*D3 + g3)*16 + c);
            else
                *d = make_float4(0.f, 0.f, 0.f, 0.f);
        }
        if (tid < 162)
            cp_async16(wdst + tid, (const float4*)(wgt + ci*648) + tid);
    };

    float2 acc[3][8];
    #pragma unroll
    for (int co = 0; co < 3; ++co)
        #pragma unroll
        for (int m = 0; m < 8; ++m) acc[co][m] = make_float2(0.f, 0.f);

    stage(0, buf0, wbuf0);
    asm volatile("cp.async.commit_group;" ::: "memory");

    for (int ci = 0; ci < 6; ++ci) {
        if (ci + 1 < 6) {
            stage(ci + 1, (ci & 1) ? buf0 : buf1, (ci & 1) ? wbuf0 : wbuf1);
            asm volatile("cp.async.commit_group;" ::: "memory");
            asm volatile("cp.async.wait_group 1;" ::: "memory");
        } else {
            asm volatile("cp.async.wait_group 0;" ::: "memory");
        }
        __syncthreads();

        const float4* sIn = (ci & 1) ? buf1 : buf0;
        const float*  sWf = (const float*)((ci & 1) ? wbuf1 : wbuf0);

        #pragma unroll 1
        for (int k1 = 0; k1 < 3; ++k1) {
            #pragma unroll
            for (int k23 = 0; k23 < 9; ++k23) {
                const int k2 = k23 / 3, k3 = k23 % 3;
                const float4* up = sIn
                    + (((x1l + k1)*6 + (x2l + k2))*10 + (x3l + k3))*17 + q*4;
                float4 ua[4];
                #pragma unroll
                for (int m = 0; m < 4; ++m) ua[m] = up[m];
                const float2* uf = reinterpret_cast<const float2*>(ua);

                const float4* wp = (const float4*)(sWf + (k1*9 + k23)*24);
                #pragma unroll
                for (int co = 0; co < 3; ++co) {
                    float4 wa = wp[co*2];
                    float4 wb = wp[co*2 + 1];
                    acc[co][0] = ffma2(uf[0], make_float2(wa.x,wa.x), acc[co][0]);
                    acc[co][1] = ffma2(uf[1], make_float2(wa.y,wa.y), acc[co][1]);
                    acc[co][2] = ffma2(uf[2], make_float2(wa.z,wa.z), acc[co][2]);
                    acc[co][3] = ffma2(uf[3], make_float2(wa.w,wa.w), acc[co][3]);
                    acc[co][4] = ffma2(uf[4], make_float2(wb.x,wb.x), acc[co][4]);
                    acc[co][5] = ffma2(uf[5], make_float2(wb.y,wb.y), acc[co][5]);
                    acc[co][6] = ffma2(uf[6], make_float2(wb.z,wb.z), acc[co][6]);
                    acc[co][7] = ffma2(uf[7], make_float2(wb.w,wb.w), acc[co][7]);
                }
            }
        }
        __syncthreads();   // protect buf[ci&1] before it is re-staged
    }

    // inverse transform A^T m + bias (validated R8/R9)
    const int x1 = x1g + x1l, x2 = x2g + x2l, x3 = x3g + x3l;
    const int base = ((x1*D2 + x2)*D3 + x3)*D4 + q*6;
    #pragma unroll
    for (int co = 0; co < 3; ++co) {
        float bsc = __ldg(bias + co);
        float2 bb = make_float2(bsc, bsc);
        float2* m = acc[co];
        float2 s1 = fadd2(m[1], m[2]), d1 = fsub2(m[1], m[2]);
        float2 s3 = fadd2(m[3], m[4]), d3 = fsub2(m[3], m[4]);
        float2 s5 = fadd2(m[5], m[6]), d5 = fsub2(m[5], m[6]);
        float2 y[6];
        y[0] = fadd2(fadd2(fadd2(m[0], s1), fadd2(s3, s5)), bb);
        y[1] = ffma2(d3, make_float2(2.f,2.f),
               ffma2(d5, make_float2(0.5f,0.5f), fadd2(d1, bb)));
        y[2] = ffma2(s3, make_float2(4.f,4.f),
               ffma2(s5, make_float2(0.25f,0.25f), fadd2(s1, bb)));
        y[3] = ffma2(d3, make_float2(8.f,8.f),
               ffma2(d5, make_float2(0.125f,0.125f), fadd2(d1, bb)));
        y[4] = ffma2(s3, make_float2(16.f,16.f),
               ffma2(s5, make_float2(0.0625f,0.0625f), fadd2(s1, bb)));
        y[5] = ffma2(d3, make_float2(32.f,32.f),
               ffma2(d5, make_float2(0.03125f,0.03125f),
               fadd2(fadd2(d1, m[7]), bb)));
        float4* op = (float4*)(out + co*NSP + base);
        #pragma unroll
        for (int j2 = 0; j2 < 3; ++j2)
            op[j2] = make_float4(y[2*j2].x, y[2*j2].y,
                                 y[2*j2+1].x, y[2*j2+1].y);
    }
}

// ---------------------------------------------------------------------------
// W1 conv  [UNCHANGED — R7/R9 passing]
// ---------------------------------------------------------------------------
#define W1_W_F2     (81*4)
#define W1_STAGE_F2 (240*26)
#define W1_SMEM     ((W1_W_F2 + W1_STAGE_F2)*8)

__global__ __launch_bounds__(256, 3) void w1_kernel(
    const float2* __restrict__ g,
    const float*  __restrict__ W,  const float* __restrict__ bias,
    float2* __restrict__ out)
{
    extern __shared__ float2 dsm[];
    float2* sW  = dsm;
    float2* sIn = dsm + W1_W_F2;

    const int tid = threadIdx.x;
    const int x3l = tid & 7;
    const int q   = (tid >> 3) & 3;
    const int x2l = (tid >> 5) & 3;
    const int x1l = tid >> 7;
    const int x1g = blockIdx.x * 2;
    const int x2g = blockIdx.y * 4;
    const int x3g = blockIdx.z * 8;

    for (int s = tid; s < 81*3; s += 256) {
        int grp = s / 3, co = s % 3;
        int ci = grp / 27, k = grp % 27;
        float w = W[(co*3 + ci)*27 + k];
        sW[grp*4 + co] = make_float2(w, w);
    }

    float2 acc[3][6];
    #pragma unroll
    for (int co = 0; co < 3; ++co) {
        float b = __ldg(bias + co);
        #pragma unroll
        for (int j = 0; j < 6; ++j) acc[co][j] = make_float2(b, b);
    }

    for (int ci = 0; ci < 3; ++ci) {
        const float2* __restrict__ src = g + ci * NSP;
        __syncthreads();
        for (int idx = tid; idx < 240*12; idx += 256) {
            int row = idx / 12, c = idx % 12;
            int p3 = row % 10; int t = row / 10; int p2 = t % 6; int p1 = t / 6;
            int g1 = x1g - 1 + p1, g2 = x2g - 1 + p2, g3 = x3g - 1 + p3;
            float4 v = make_float4(0.f, 0.f, 0.f, 0.f);
            if ((unsigned)g1 < (unsigned)D1 && (unsigned)g2 < (unsigned)D2 &&
                (unsigned)g3 < (unsigned)D3)
                v = ((const float4*)src)[((g1*D2 + g2)*D3 + g3)*12 + c];
            ((float4*)sIn)[row*13 + c] = v;
        }
        __syncthreads();

        const float2* wci = sW + ci * 108;
        #pragma unroll 1
        for (int k1 = 0; k1 < 3; ++k1) {
            #pragma unroll
            for (int k23 = 0; k23 < 9; ++k23) {
                const int k2 = k23 / 3, k3 = k23 % 3;
                const float4* ip = (const float4*)sIn
                    + (((x1l + k1)*6 + (x2l + k2))*10 + (x3l + k3))*13 + q*3;
                float4 a4[3];
                #pragma unroll
                for (int m = 0; m < 3; ++m) a4[m] = ip[m];
                const float2* uf = reinterpret_cast<const float2*>(a4);

                const float2* wp = wci + (k1*9 + k23)*4;
                float2 w0 = wp[0];
                float2 w1 = wp[1];
                float2 w2 = wp[2];
                #pragma unroll
                for (int j = 0; j < 6; ++j) {
                    acc[0][j] = ffma2(uf[j], w0, acc[0][j]);
                    acc[1][j] = ffma2(uf[j], w1, acc[1][j]);
                    acc[2][j] = ffma2(uf[j], w2, acc[2][j]);
                }
            }
        }
    }

    const int x1 = x1g + x1l, x2 = x2g + x2l, x3 = x3g + x3l;
    const int base = ((x1*D2 + x2)*D3 + x3)*D4 + q*6;
    #pragma unroll
    for (int co = 0; co < 3; ++co) {
        float4* op = (float4*)(out + co*NSP + base);
        #pragma unroll
        for (int j2 = 0; j2 < 3; ++j2)
            op[j2] = make_float4(acc[co][2*j2].x,   acc[co][2*j2].y,
                                 acc[co][2*j2+1].x, acc[co][2*j2+1].y);
    }
}

// ---------------------------------------------------------------------------
// Fused epilogue + x4 transform (w2b):
//   out = conv(t, W2, pad x4) + b2 + conv(cur, Wd) + bd   [w2wd math, R1+]
//   non-final: write out AND u = B^T(out) (halo via shfl; replaces bx)
//   final:     de-interleaved write to ofinal
// Thread = (row, group g). 6 outputs/thread -> cur read = exactly 3 float4.
// ---------------------------------------------------------------------------
__global__ __launch_bounds__(256) void w2b_kernel(
    const float2* __restrict__ t,  const float2* __restrict__ cur,
    const float*  __restrict__ W2, const float* __restrict__ b2,
    const float*  __restrict__ Wd, const float* __restrict__ bd,
    float2* __restrict__ onew, float2* __restrict__ ubuf,
    float* __restrict__ ofinal, int final_layer)
{
    const int tid = threadIdx.x;
    const size_t row = (size_t)blockIdx.x * 64 + (tid >> 2);
    const int g = tid & 3;
    const float2 z = make_float2(0.f, 0.f);

    float w2r[3][3][3], wdr[3][3];
    #pragma unroll
    for (int co = 0; co < 3; ++co)
        #pragma unroll
        for (int ci = 0; ci < 3; ++ci) {
            #pragma unroll
            for (int k = 0; k < 3; ++k)
                w2r[co][ci][k] = __ldg(W2 + (co*3 + ci)*3 + k);
            wdr[co][ci] = __ldg(Wd + co*3 + ci);
        }

    float2 r12[3][6];
    #pragma unroll
    for (int co = 0; co < 3; ++co) {
        float b = __ldg(b2 + co) + __ldg(bd + co);
        #pragma unroll
        for (int j = 0; j < 6; ++j) r12[co][j] = make_float2(b, b);
    }

    #pragma unroll
    for (int ci = 0; ci < 3; ++ci) {
        const float2* tp = t + (size_t)ci*NSP + row*D4;
        float2 tv[8];                      // t[6g-1 .. 6g+6]
        #pragma unroll
        for (int e = 0; e < 8; ++e) {
            int x4 = 6*g - 1 + e;
            tv[e] = ((unsigned)x4 < (unsigned)D4) ? tp[x4] : z;
        }
        const float4* cp = (const float4*)(cur + (size_t)ci*NSP + row*D4) + g*3;
        float4 c4[3];                      // cur[6g .. 6g+5] : 6 f2 = 3 f4
        #pragma unroll
        for (int m = 0; m < 3; ++m) c4[m] = cp[m];
        const float2* cf = reinterpret_cast<const float2*>(c4);

        #pragma unroll
        for (int co = 0; co < 3; ++co) {
            float2 w0 = make_float2(w2r[co][ci][0], w2r[co][ci][0]);
            float2 w1 = make_float2(w2r[co][ci][1], w2r[co][ci][1]);
            float2 w2v = make_float2(w2r[co][ci][2], w2r[co][ci][2]);
            float2 wd = make_float2(wdr[co][ci], wdr[co][ci]);
            #pragma unroll
            for (int j = 0; j < 6; ++j) {
                float2 a = r12[co][j];
                a = ffma2(tv[j],     w0,  a);
                a = ffma2(tv[j + 1], w1,  a);
                a = ffma2(tv[j + 2], w2v, a);
                a = ffma2(cf[j],     wd,  a);
                r12[co][j] = a;
            }
        }
    }

    if (final_layer) {
        #pragma unroll
        for (int co = 0; co < 3; ++co) {
            float2* o0 = (float2*)(ofinal + (size_t)co*NSP + row*D4 + g*6);
            float2* o1 = (float2*)(ofinal + CN + (size_t)co*NSP + row*D4 + g*6);
            #pragma unroll
            for (int m = 0; m < 3; ++m) {
                o0[m] = make_float2(r12[co][2*m].x, r12[co][2*m + 1].x);
                o1[m] = make_float2(r12[co][2*m].y, r12[co][2*m + 1].y);
            }
        }
        return;
    }

    // write layer output
    #pragma unroll
    for (int co = 0; co < 3; ++co) {
        float4* op = (float4*)(onew + (size_t)co*NSP + row*D4) + g*3;
        #pragma unroll
        for (int m = 0; m < 3; ++m)
            op[m] = make_float4(r12[co][2*m].x,   r12[co][2*m].y,
                                r12[co][2*m+1].x, r12[co][2*m+1].y);
    }

    // x4-halo of out via shfl (lane g-1 / g+1 hold adjacent groups of same row)
    #pragma unroll
    for (int co = 0; co < 3; ++co) {
        float lox = __shfl_up_sync(0xffffffffu, r12[co][5].x, 1);
        float loy = __shfl_up_sync(0xffffffffu, r12[co][5].y, 1);
        float hix = __shfl_down_sync(0xffffffffu, r12[co][0].x, 1);
        float hiy = __shfl_down_sync(0xffffffffu, r12[co][0].y, 1);
        float2 x[8];
        x[0] = (g > 0) ? make_float2(lox, loy) : z;   // x4 = 6g-1 (pad at -1)
        #pragma unroll
        for (int j = 0; j < 6; ++j) x[j + 1] = r12[co][j];
        x[7] = (g < 3) ? make_float2(hix, hiy) : z;   // x4 = 6g+6 (pad at 24)
        float2 u[8];
        btrans8(x, u);
        float4* d = (float4*)(ubuf + ((size_t)co*NROW + row)*32) + g*4;
        #pragma unroll
        for (int m = 0; m < 4; ++m)
            d[m] = make_float4(u[2*m].x, u[2*m].y, u[2*m+1].x, u[2*m+1].y);
    }
}

// ---------------------------------------------------------------------------
// Driver
// ---------------------------------------------------------------------------
extern "C" void kernel_launch(void* const* d_in, const int* in_sizes, int n_in,
                              void* d_out, int out_size)
{
    const float* f   = (const float*)d_in[0];
    const float* bnd = (const float*)d_in[1];
    const float* Wg  = (const float*)d_in[2];
    const float* bg  = (const float*)d_in[3];
    const float* W1  = (const float*)d_in[4];
    const float* b1  = (const float*)d_in[5];
    const float* W2  = (const float*)d_in[6];
    const float* b2  = (const float*)d_in[7];
    const float* Wd  = (const float*)d_in[8];
    const float* bd  = (const float*)d_in[9];

    static bool attr_done = false;
    if (!attr_done) {
        cudaFuncSetAttribute(wg_kernel,
            cudaFuncAttributeMaxDynamicSharedMemorySize, WG_SMEM);
        cudaFuncSetAttribute(w1_kernel,
            cudaFuncAttributeMaxDynamicSharedMemorySize, W1_SMEM);
        attr_done = true;
    }

    float2 *fi, *bi, *gg, *tt, *oA, *oB, *ub;
    float *wtf;
    cudaGetSymbolAddress((void**)&fi, s_fi);
    cudaGetSymbolAddress((void**)&bi, s_bi);
    cudaGetSymbolAddress((void**)&gg, s_g);
    cudaGetSymbolAddress((void**)&tt, s_t);
    cudaGetSymbolAddress((void**)&oA, s_oA);
    cudaGetSymbolAddress((void**)&oB, s_oB);
    cudaGetSymbolAddress((void**)&ub, s_u);
    cudaGetSymbolAddress((void**)&wtf, s_wgtf);

    pack_kernel<<<(CN/4 + 255) / 256, 256>>>(
        (const float4*)f, (const float4*)bnd, (float4*)fi, (float4*)bi,
        Wg, wtf);

    // one-time transforms: f -> u[0..2] (layer-0 input), boundary -> u[3..5]
    bx_kernel<<<dim3(NROW/64, 3), 256>>>(fi, ub);
    bx_kernel<<<dim3(NROW/64, 3), 256>>>(bi, ub + (size_t)3*NROW*32);
    // launch order: harness(2) + pack + 2x bx => first wg in ncu -s 5 slot

    dim3 ggrid(D1/4, D2/4, D3/8);      // wg: 12 x 12 x 6 = 864 blocks
    dim3 cgrid(D1/2, D2/4, D3/8);      // w1
    const float2* cur = fi;
    float2* outs[LAYERS] = {oA, oB, oA, nullptr};

    for (int i = 0; i < LAYERS; ++i) {
        wg_kernel<<<ggrid, 512, WG_SMEM>>>(
            ub, wtf + i*3888, bg + i*3, gg);
        w1_kernel<<<cgrid, 256, W1_SMEM>>>(
            gg, W1 + i*243, b1 + i*3, tt);
        w2b_kernel<<<NROW/64, 256>>>(
            tt, cur, W2 + i*27, b2 + i*3, Wd + i*9, bd + i*3,
            outs[i], ub, (float*)d_out, (i == LAYERS - 1) ? 1 : 0);
        cur = outs[i];
    }
}

// round 14
// speedup vs baseline: 2.2157x; 1.0394x over previous
#include <cuda_runtime.h>
#include <cuda_bf16.h>

// ---------------------------------------------------------------------------
// Problem constants
// ---------------------------------------------------------------------------
#define LAYERS 4
#define NC 3
#define D1 48
#define D2 48
#define D3 48
#define D4 24
#define NROW (D1*D2*D3)           // 110,592 x4-rows per channel
#define NSP  (D1*D2*D3*D4)        // 2,654,208 spatial points per channel
#define CN   (NC*NSP)             // 7,962,624 elems per batch image

// Scratch: batch-interleaved tensors, float2 = {b0, b1}
__device__ float2 s_fi[CN];
__device__ float2 s_bi[CN];
__device__ float2 s_g [CN];
__device__ float2 s_oA[CN];
__device__ float2 s_oB[CN];
// x4-Winograd-transformed inputs: [ci 0..5][row][group*8+point] f2
__device__ float2 s_u[6*(size_t)NROW*32];
// Winograd-transformed Wg weights, scalar: [L][ci][k123][co*8+p]
__device__ float s_wgtf[LAYERS*6*27*24];

// ---- packed f32x2 ops ------------------------------------------------------
__device__ __forceinline__ float2 ffma2(float2 a, float2 b, float2 c) {
    unsigned long long ua, ub, uc, ud;
    ua = *reinterpret_cast<const unsigned long long*>(&a);
    ub = *reinterpret_cast<const unsigned long long*>(&b);
    uc = *reinterpret_cast<const unsigned long long*>(&c);
    asm("fma.rn.f32x2 %0, %1, %2, %3;" : "=l"(ud) : "l"(ua), "l"(ub), "l"(uc));
    return *reinterpret_cast<float2*>(&ud);
}
__device__ __forceinline__ float2 fadd2(float2 a, float2 b) {
    unsigned long long ua, ub, ud;
    ua = *reinterpret_cast<const unsigned long long*>(&a);
    ub = *reinterpret_cast<const unsigned long long*>(&b);
    asm("add.rn.f32x2 %0, %1, %2;" : "=l"(ud) : "l"(ua), "l"(ub));
    return *reinterpret_cast<float2*>(&ud);
}
__device__ __forceinline__ float2 fsub2(float2 a, float2 b) {   // a - b
    return ffma2(b, make_float2(-1.f, -1.f), a);
}
__device__ __forceinline__ void cp_async16(void* smem, const void* gmem) {
    unsigned sa = (unsigned)__cvta_generic_to_shared(smem);
    asm volatile("cp.async.cg.shared.global [%0], [%1], 16;"
                 :: "r"(sa), "l"(gmem) : "memory");
}

// B^T (F(6,3), points {0,±1,±2,±1/2,inf}) — validated R8/R9
__device__ __forceinline__ void btrans8(const float2* x, float2* u) {
    const float2 z = make_float2(0.f, 0.f);
    u[0] = ffma2(fsub2(x[4], x[2]), make_float2(5.25f,5.25f), fsub2(x[0], x[6]));
    u[7] = ffma2(fsub2(x[3], x[5]), make_float2(5.25f,5.25f), fsub2(x[7], x[1]));
    {
        float2 e = ffma2(x[4], make_float2(-4.25f,-4.25f), fadd2(x[2], x[6]));
        float2 o = ffma2(x[3], make_float2(-4.25f,-4.25f), fadd2(x[1], x[5]));
        u[1] = fadd2(e, o);
        u[2] = fsub2(e, o);
    }
    {
        float2 e = ffma2(x[2], make_float2(0.25f,0.25f),
                   ffma2(x[4], make_float2(-1.25f,-1.25f), x[6]));
        float2 o = ffma2(x[1], make_float2(0.5f,0.5f),
                   ffma2(x[3], make_float2(-2.5f,-2.5f),
                   ffma2(x[5], make_float2(2.f,2.f), z)));
        u[3] = fadd2(e, o);
        u[4] = fsub2(e, o);
    }
    {
        float2 e = ffma2(x[2], make_float2(4.f,4.f),
                   ffma2(x[4], make_float2(-5.f,-5.f), x[6]));
        float2 o = ffma2(x[1], make_float2(2.f,2.f),
                   ffma2(x[3], make_float2(-2.5f,-2.5f),
                   ffma2(x[5], make_float2(0.5f,0.5f), z)));
        u[5] = fadd2(e, o);
        u[6] = fsub2(e, o);
    }
}

// ---------------------------------------------------------------------------
// Pack (+ folded Wg weight transform)   [UNCHANGED — R9 passing]
// ---------------------------------------------------------------------------
__global__ void pack_kernel(const float4* __restrict__ f,
                            const float4* __restrict__ bnd,
                            float4* __restrict__ fi,
                            float4* __restrict__ bi,
                            const float* __restrict__ Wg,
                            float* __restrict__ wtf) {
    int i = blockIdx.x * blockDim.x + threadIdx.x;
    if (i < LAYERS*6*27*3) {
        int co = i % 3;  int r = i / 3;
        int k123 = r % 27; r /= 27;
        int ci = r % 6;    int L = r / 6;
        const float* w = Wg + L*1458 + (co*6 + ci)*81 + k123*3;
        float w0 = w[0], w1 = w[1], w2 = w[2];
        float p[8];
        p[0] = w0;
        p[1] = (-2.f/9.f)  * (w0 + w1 + w2);
        p[2] = (-2.f/9.f)  * (w0 - w1 + w2);
        p[3] = (1.f/90.f)*w0 + (1.f/45.f)*w1 + (2.f/45.f)*w2;
        p[4] = (1.f/90.f)*w0 - (1.f/45.f)*w1 + (2.f/45.f)*w2;
        p[5] = (32.f/45.f)*w0 + (16.f/45.f)*w1 + (8.f/45.f)*w2;
        p[6] = (32.f/45.f)*w0 - (16.f/45.f)*w1 + (8.f/45.f)*w2;
        p[7] = w2;
        float* o = wtf + ((L*6 + ci)*27 + k123)*24 + co*8;
        #pragma unroll
        for (int m = 0; m < 8; ++m) o[m] = p[m];
    }
    if (i >= CN / 4) return;
    float4 a = f[i],   b = f[i + CN / 4];
    fi[2*i]     = make_float4(a.x, b.x, a.y, b.y);
    fi[2*i + 1] = make_float4(a.z, b.z, a.w, b.w);
    a = bnd[i]; b = bnd[i + CN / 4];
    bi[2*i]     = make_float4(a.x, b.x, a.y, b.y);
    bi[2*i + 1] = make_float4(a.z, b.z, a.w, b.w);
}

// ---------------------------------------------------------------------------
// x4 input transform, global -> global (once for f, once for boundary)
// [UNCHANGED — R9 passing]
// ---------------------------------------------------------------------------
__global__ __launch_bounds__(256) void bx_kernel(
    const float2* __restrict__ src, float2* __restrict__ dst)
{
    __shared__ float4 sraw[64*13];
    const int ch   = blockIdx.y;
    const int row0 = blockIdx.x * 64;
    const float4* s = (const float4*)(src + (size_t)ch*NSP + (size_t)row0*D4);
    for (int idx = threadIdx.x; idx < 768; idx += 256) {
        int r = idx / 12, c = idx % 12;
        sraw[r*13 + c] = s[idx];
    }
    __syncthreads();

    const int r = threadIdx.x >> 2, g = threadIdx.x & 3;
    const float2* rp = (const float2*)&sraw[r*13];
    const float2 z = make_float2(0.f, 0.f);
    float2 x[8];
    #pragma unroll
    for (int e = 0; e < 8; ++e) {
        int x4 = 6*g - 1 + e;
        x[e] = ((unsigned)x4 < (unsigned)D4) ? rp[x4] : z;
    }
    float2 u[8];
    btrans8(x, u);
    float4* d = (float4*)(dst + ((size_t)(ch*NROW + row0 + r))*32) + g*4;
    #pragma unroll
    for (int m = 0; m < 4; ++m)
        d[m] = make_float4(u[2*m].x, u[2*m].y, u[2*m+1].x, u[2*m+1].y);
}

// ---------------------------------------------------------------------------
// Wg conv in Winograd(x4) domain  [UNCHANGED — R13, 300 us measured]
// ---------------------------------------------------------------------------
#define WG_BUF_F4  (360*17)                            // 6120 f4 per buffer
#define WG_W_F4    162                                 // per-ci weights (f4)
#define WG_SMEM    ((2*WG_BUF_F4 + 2*WG_W_F4)*16)      // 201024 B

__global__ __launch_bounds__(512, 1) void wg_kernel(
    const float2* __restrict__ ubuf,
    const float*  __restrict__ wgt,
    const float*  __restrict__ bias,
    float2* __restrict__ out)
{
    extern __shared__ float4 dsm4[];
    float4* buf0  = dsm4;
    float4* buf1  = dsm4 + WG_BUF_F4;
    float4* wbuf0 = dsm4 + 2*WG_BUF_F4;
    float4* wbuf1 = dsm4 + 2*WG_BUF_F4 + WG_W_F4;

    const int tid = threadIdx.x;
    const int x3l = tid & 7;
    const int q   = (tid >> 3) & 3;
    const int x2l = (tid >> 5) & 3;
    const int x1l = (tid >> 7) & 3;
    const int x1g = blockIdx.x * 4;
    const int x2g = blockIdx.y * 4;
    const int x3g = blockIdx.z * 8;

    auto stage = [&](int ci, float4* dst, float4* wdst) {
        const float4* usrc = (const float4*)(ubuf + (size_t)ci*NROW*32);
        for (int idx = tid; idx < 360*16; idx += 512) {
            int r = idx >> 4, c = idx & 15;
            int p3 = r % 10; int t = r / 10; int p2 = t % 6; int p1 = t / 6;
            int g1 = x1g - 1 + p1, g2 = x2g - 1 + p2, g3 = x3g - 1 + p3;
            float4* d = dst + r*17 + c;
            if ((unsigned)g1 < (unsigned)D1 && (unsigned)g2 < (unsigned)D2 &&
                (unsigned)g3 < (unsigned)D3)
                cp_async16(d, usrc + (size_t)((g1*D2 + g2)*D3 + g3)*16 + c);
            else
                *d = make_float4(0.f, 0.f, 0.f, 0.f);
        }
        if (tid < 162)
            cp_async16(wdst + tid, (const float4*)(wgt + ci*648) + tid);
    };

    float2 acc[3][8];
    #pragma unroll
    for (int co = 0; co < 3; ++co)
        #pragma unroll
        for (int m = 0; m < 8; ++m) acc[co][m] = make_float2(0.f, 0.f);

    stage(0, buf0, wbuf0);
    asm volatile("cp.async.commit_group;" ::: "memory");

    for (int ci = 0; ci < 6; ++ci) {
        if (ci + 1 < 6) {
            stage(ci + 1, (ci & 1) ? buf0 : buf1, (ci & 1) ? wbuf0 : wbuf1);
            asm volatile("cp.async.commit_group;" ::: "memory");
            asm volatile("cp.async.wait_group 1;" ::: "memory");
        } else {
            asm volatile("cp.async.wait_group 0;" ::: "memory");
        }
        __syncthreads();

        const float4* sIn = (ci & 1) ? buf1 : buf0;
        const float*  sWf = (const float*)((ci & 1) ? wbuf1 : wbuf0);

        #pragma unroll 1
        for (int k1 = 0; k1 < 3; ++k1) {
            #pragma unroll
            for (int k23 = 0; k23 < 9; ++k23) {
                const int k2 = k23 / 3, k3 = k23 % 3;
                const float4* up = sIn
                    + (((x1l + k1)*6 + (x2l + k2))*10 + (x3l + k3))*17 + q*4;
                float4 ua[4];
                #pragma unroll
                for (int m = 0; m < 4; ++m) ua[m] = up[m];
                const float2* uf = reinterpret_cast<const float2*>(ua);

                const float4* wp = (const float4*)(sWf + (k1*9 + k23)*24);
                #pragma unroll
                for (int co = 0; co < 3; ++co) {
                    float4 wa = wp[co*2];
                    float4 wb = wp[co*2 + 1];
                    acc[co][0] = ffma2(uf[0], make_float2(wa.x,wa.x), acc[co][0]);
                    acc[co][1] = ffma2(uf[1], make_float2(wa.y,wa.y), acc[co][1]);
                    acc[co][2] = ffma2(uf[2], make_float2(wa.z,wa.z), acc[co][2]);
                    acc[co][3] = ffma2(uf[3], make_float2(wa.w,wa.w), acc[co][3]);
                    acc[co][4] = ffma2(uf[4], make_float2(wb.x,wb.x), acc[co][4]);
                    acc[co][5] = ffma2(uf[5], make_float2(wb.y,wb.y), acc[co][5]);
                    acc[co][6] = ffma2(uf[6], make_float2(wb.z,wb.z), acc[co][6]);
                    acc[co][7] = ffma2(uf[7], make_float2(wb.w,wb.w), acc[co][7]);
                }
            }
        }
        __syncthreads();
    }

    const int x1 = x1g + x1l, x2 = x2g + x2l, x3 = x3g + x3l;
    const int base = ((x1*D2 + x2)*D3 + x3)*D4 + q*6;
    #pragma unroll
    for (int co = 0; co < 3; ++co) {
        float bsc = __ldg(bias + co);
        float2 bb = make_float2(bsc, bsc);
        float2* m = acc[co];
        float2 s1 = fadd2(m[1], m[2]), d1 = fsub2(m[1], m[2]);
        float2 s3 = fadd2(m[3], m[4]), d3 = fsub2(m[3], m[4]);
        float2 s5 = fadd2(m[5], m[6]), d5 = fsub2(m[5], m[6]);
        float2 y[6];
        y[0] = fadd2(fadd2(fadd2(m[0], s1), fadd2(s3, s5)), bb);
        y[1] = ffma2(d3, make_float2(2.f,2.f),
               ffma2(d5, make_float2(0.5f,0.5f), fadd2(d1, bb)));
        y[2] = ffma2(s3, make_float2(4.f,4.f),
               ffma2(s5, make_float2(0.25f,0.25f), fadd2(s1, bb)));
        y[3] = ffma2(d3, make_float2(8.f,8.f),
               ffma2(d5, make_float2(0.125f,0.125f), fadd2(d1, bb)));
        y[4] = ffma2(s3, make_float2(16.f,16.f),
               ffma2(s5, make_float2(0.0625f,0.0625f), fadd2(s1, bb)));
        y[5] = ffma2(d3, make_float2(32.f,32.f),
               ffma2(d5, make_float2(0.03125f,0.03125f),
               fadd2(fadd2(d1, m[7]), bb)));
        float4* op = (float4*)(out + co*NSP + base);
        #pragma unroll
        for (int j2 = 0; j2 < 3; ++j2)
            op[j2] = make_float4(y[2*j2].x, y[2*j2].y,
                                 y[2*j2+1].x, y[2*j2+1].y);
    }
}

// ---------------------------------------------------------------------------
// Fused W1 + W2/Wd epilogue + x4 transform (w1f):
//   t   = conv(g, W1, pad(1,1,1,0)) + b1      -> registers only (never global)
//   out = conv(t, W2, pad x4 1) + b2 + Wd*cur + bd
//   non-final: write out and u = B^T(out); final: de-interleave to ofinal.
// t x4-halo and out x4-halo via shfl +-8 (q = tid bits 3..4, warp-local).
// Input staging double-buffered via cp.async. (256,2): 128-reg budget.
// ---------------------------------------------------------------------------
#define W1_BUF_F4 (240*13)                          // 3120 f4 per buffer
#define W1_SMEM   (324*8 + 2*W1_BUF_F4*16)          // 2592 + 99840 = 102432 B

__global__ __launch_bounds__(256, 2) void w1f_kernel(
    const float2* __restrict__ g,   const float2* __restrict__ cur,
    const float*  __restrict__ W1w, const float* __restrict__ b1,
    const float*  __restrict__ W2w, const float* __restrict__ b2,
    const float*  __restrict__ Wdw, const float* __restrict__ bd,
    float2* __restrict__ onew, float2* __restrict__ ubuf,
    float* __restrict__ ofinal, int final_layer)
{
    extern __shared__ float2 dsm[];
    float2* sW   = dsm;                              // [ci*27+k][4]
    float4* buf0 = (float4*)(dsm + 324);
    float4* buf1 = buf0 + W1_BUF_F4;

    const int tid = threadIdx.x;
    const int x3l = tid & 7;
    const int q   = (tid >> 3) & 3;
    const int x2l = (tid >> 5) & 3;
    const int x1l = tid >> 7;
    const int x1g = blockIdx.x * 2;
    const int x2g = blockIdx.y * 4;
    const int x3g = blockIdx.z * 8;
    const float2 z = make_float2(0.f, 0.f);

    // all W1 weights up front (dup'd f2)
    for (int s = tid; s < 81*3; s += 256) {
        int grp = s / 3, co = s % 3;
        int ci = grp / 27, k = grp % 27;
        float w = W1w[(co*3 + ci)*27 + k];
        sW[grp*4 + co] = make_float2(w, w);
    }

    auto stage = [&](int ci, float4* dst) {
        const float4* src = (const float4*)(g + (size_t)ci*NSP);
        for (int idx = tid; idx < 240*12; idx += 256) {
            int row = idx / 12, c = idx % 12;
            int p3 = row % 10; int t = row / 10; int p2 = t % 6; int p1 = t / 6;
            int g1 = x1g - 1 + p1, g2 = x2g - 1 + p2, g3 = x3g - 1 + p3;
            float4* d = dst + row*13 + c;
            if ((unsigned)g1 < (unsigned)D1 && (unsigned)g2 < (unsigned)D2 &&
                (unsigned)g3 < (unsigned)D3)
                cp_async16(d, src + (size_t)((g1*D2 + g2)*D3 + g3)*12 + c);
            else
                *d = make_float4(0.f, 0.f, 0.f, 0.f);
        }
    };

    float2 acc[3][6];
    #pragma unroll
    for (int co = 0; co < 3; ++co) {
        float b = __ldg(b1 + co);
        #pragma unroll
        for (int j = 0; j < 6; ++j) acc[co][j] = make_float2(b, b);
    }

    stage(0, buf0);
    asm volatile("cp.async.commit_group;" ::: "memory");

    for (int ci = 0; ci < 3; ++ci) {
        if (ci + 1 < 3) {
            stage(ci + 1, (ci & 1) ? buf0 : buf1);
            asm volatile("cp.async.commit_group;" ::: "memory");
            asm volatile("cp.async.wait_group 1;" ::: "memory");
        } else {
            asm volatile("cp.async.wait_group 0;" ::: "memory");
        }
        __syncthreads();

        const float4* sIn = (ci & 1) ? buf1 : buf0;
        const float2* wci = sW + ci * 108;
        #pragma unroll 1
        for (int k1 = 0; k1 < 3; ++k1) {
            #pragma unroll
            for (int k23 = 0; k23 < 9; ++k23) {
                const int k2 = k23 / 3, k3 = k23 % 3;
                const float4* ip = sIn
                    + (((x1l + k1)*6 + (x2l + k2))*10 + (x3l + k3))*13 + q*3;
                float4 a4[3];
                #pragma unroll
                for (int m = 0; m < 3; ++m) a4[m] = ip[m];
                const float2* uf = reinterpret_cast<const float2*>(a4);

                const float2* wp = wci + (k1*9 + k23)*4;
                float2 w0 = wp[0];
                float2 w1 = wp[1];
                float2 w2 = wp[2];
                #pragma unroll
                for (int j = 0; j < 6; ++j) {
                    acc[0][j] = ffma2(uf[j], w0, acc[0][j]);
                    acc[1][j] = ffma2(uf[j], w1, acc[1][j]);
                    acc[2][j] = ffma2(uf[j], w2, acc[2][j]);
                }
            }
        }
        __syncthreads();   // protect buf[ci&1] before re-stage
    }

    // ---- epilogue: acc[ci][j] == t[ci][x4 = q*6 + j] -----------------------
    const int x1 = x1g + x1l, x2 = x2g + x2l, x3 = x3g + x3l;
    const size_t row = (size_t)((x1*D2 + x2)*D3 + x3);
    const size_t base = row*D4 + q*6;

    // t x4-halo via shfl +-8 (partner q-1 / q+1, same warp, same x3l)
    float2 tlo[3], thi[3];
    #pragma unroll
    for (int c = 0; c < 3; ++c) {
        float lx = __shfl_up_sync(0xffffffffu,   acc[c][5].x, 8);
        float ly = __shfl_up_sync(0xffffffffu,   acc[c][5].y, 8);
        float hx = __shfl_down_sync(0xffffffffu, acc[c][0].x, 8);
        float hy = __shfl_down_sync(0xffffffffu, acc[c][0].y, 8);
        tlo[c] = (q > 0) ? make_float2(lx, ly) : z;   // t[q*6-1], pad at -1
        thi[c] = (q < 3) ? make_float2(hx, hy) : z;   // t[q*6+6], pad at 24
    }

    float2 r12[3][6];
    #pragma unroll
    for (int co = 0; co < 3; ++co) {
        float b = __ldg(b2 + co) + __ldg(bd + co);
        #pragma unroll
        for (int j = 0; j < 6; ++j) r12[co][j] = make_float2(b, b);
    }

    #pragma unroll
    for (int ci = 0; ci < 3; ++ci) {
        float2 tv[8];                       // t[6q-1 .. 6q+6]
        tv[0] = tlo[ci];
        #pragma unroll
        for (int j = 0; j < 6; ++j) tv[j + 1] = acc[ci][j];
        tv[7] = thi[ci];

        const float4* cp = (const float4*)(cur + (size_t)ci*NSP + row*D4) + q*3;
        float4 c4[3];                       // cur[6q .. 6q+5]: 6 f2 = 3 f4
        #pragma unroll
        for (int m = 0; m < 3; ++m) c4[m] = cp[m];
        const float2* cf = reinterpret_cast<const float2*>(c4);

        #pragma unroll
        for (int co = 0; co < 3; ++co) {
            float w0s = __ldg(W2w + (co*3 + ci)*3 + 0);
            float w1s = __ldg(W2w + (co*3 + ci)*3 + 1);
            float w2s = __ldg(W2w + (co*3 + ci)*3 + 2);
            float wds = __ldg(Wdw + co*3 + ci);
            float2 w0 = make_float2(w0s, w0s);
            float2 w1 = make_float2(w1s, w1s);
            float2 w2 = make_float2(w2s, w2s);
            float2 wd = make_float2(wds, wds);
            #pragma unroll
            for (int j = 0; j < 6; ++j) {
                float2 a = r12[co][j];
                a = ffma2(tv[j],     w0, a);
                a = ffma2(tv[j + 1], w1, a);
                a = ffma2(tv[j + 2], w2, a);
                a = ffma2(cf[j],     wd, a);
                r12[co][j] = a;
            }
        }
    }

    if (final_layer) {
        #pragma unroll
        for (int co = 0; co < 3; ++co) {
            float2* o0 = (float2*)(ofinal + (size_t)co*NSP + base);
            float2* o1 = (float2*)(ofinal + CN + (size_t)co*NSP + base);
            #pragma unroll
            for (int m = 0; m < 3; ++m) {
                o0[m] = make_float2(r12[co][2*m].x, r12[co][2*m + 1].x);
                o1[m] = make_float2(r12[co][2*m].y, r12[co][2*m + 1].y);
            }
        }
        return;
    }

    // write layer output
    #pragma unroll
    for (int co = 0; co < 3; ++co) {
        float4* op = (float4*)(onew + (size_t)co*NSP + row*D4) + q*3;
        #pragma unroll
        for (int m = 0; m < 3; ++m)
            op[m] = make_float4(r12[co][2*m].x,   r12[co][2*m].y,
                                r12[co][2*m+1].x, r12[co][2*m+1].y);
    }

    // x4-halo of out via shfl, then B^T, write u (next layer's wg input)
    #pragma unroll
    for (int co = 0; co < 3; ++co) {
        float lox = __shfl_up_sync(0xffffffffu,   r12[co][5].x, 8);
        float loy = __shfl_up_sync(0xffffffffu,   r12[co][5].y, 8);
        float hix = __shfl_down_sync(0xffffffffu, r12[co][0].x, 8);
        float hiy = __shfl_down_sync(0xffffffffu, r12[co][0].y, 8);
        float2 x[8];
        x[0] = (q > 0) ? make_float2(lox, loy) : z;
        #pragma unroll
        for (int j = 0; j < 6; ++j) x[j + 1] = r12[co][j];
        x[7] = (q < 3) ? make_float2(hix, hiy) : z;
        float2 u[8];
        btrans8(x, u);
        float4* d = (float4*)(ubuf + ((size_t)co*NROW + row)*32) + q*4;
        #pragma unroll
        for (int m = 0; m < 4; ++m)
            d[m] = make_float4(u[2*m].x, u[2*m].y, u[2*m+1].x, u[2*m+1].y);
    }
}

// ---------------------------------------------------------------------------
// Driver
// ---------------------------------------------------------------------------
extern "C" void kernel_launch(void* const* d_in, const int* in_sizes, int n_in,
                              void* d_out, int out_size)
{
    const float* f   = (const float*)d_in[0];
    const float* bnd = (const float*)d_in[1];
    const float* Wg  = (const float*)d_in[2];
    const float* bg  = (const float*)d_in[3];
    const float* W1  = (const float*)d_in[4];
    const float* b1  = (const float*)d_in[5];
    const float* W2  = (const float*)d_in[6];
    const float* b2  = (const float*)d_in[7];
    const float* Wd  = (const float*)d_in[8];
    const float* bd  = (const float*)d_in[9];

    static bool attr_done = false;
    if (!attr_done) {
        cudaFuncSetAttribute(wg_kernel,
            cudaFuncAttributeMaxDynamicSharedMemorySize, WG_SMEM);
        cudaFuncSetAttribute(w1f_kernel,
            cudaFuncAttributeMaxDynamicSharedMemorySize, W1_SMEM);
        attr_done = true;
    }

    float2 *fi, *bi, *gg, *oA, *oB, *ub;
    float *wtf;
    cudaGetSymbolAddress((void**)&fi, s_fi);
    cudaGetSymbolAddress((void**)&bi, s_bi);
    cudaGetSymbolAddress((void**)&gg, s_g);
    cudaGetSymbolAddress((void**)&oA, s_oA);
    cudaGetSymbolAddress((void**)&oB, s_oB);
    cudaGetSymbolAddress((void**)&ub, s_u);
    cudaGetSymbolAddress((void**)&wtf, s_wgtf);

    pack_kernel<<<(CN/4 + 255) / 256, 256>>>(
        (const float4*)f, (const float4*)bnd, (float4*)fi, (float4*)bi,
        Wg, wtf);

    // one-time transforms: f -> u[0..2], boundary -> u[3..5]
    bx_kernel<<<dim3(NROW/64, 3), 256>>>(fi, ub);
    bx_kernel<<<dim3(NROW/64, 3), 256>>>(bi, ub + (size_t)3*NROW*32);
    // launch order: harness(2) + pack + 2x bx => first wg in ncu -s 5 slot

    dim3 ggrid(D1/4, D2/4, D3/8);      // wg
    dim3 cgrid(D1/2, D2/4, D3/8);      // w1f
    const float2* cur = fi;
    float2* outs[LAYERS] = {oA, oB, oA, nullptr};

    for (int i = 0; i < LAYERS; ++i) {
        wg_kernel<<<ggrid, 512, WG_SMEM>>>(
            ub, wtf + i*3888, bg + i*3, gg);
        w1f_kernel<<<cgrid, 256, W1_SMEM>>>(
            gg, cur, W1 + i*243, b1 + i*3, W2 + i*27, b2 + i*3,
            Wd + i*9, bd + i*3,
            outs[i], ub, (float*)d_out, (i == LAYERS - 1) ? 1 : 0);
        cur = outs[i];
    }
}

// round 15
// speedup vs baseline: 2.4085x; 1.0870x over previous
#include <cuda_runtime.h>
#include <cuda_bf16.h>

// ---------------------------------------------------------------------------
// Problem constants
// ---------------------------------------------------------------------------
#define LAYERS 4
#define NC 3
#define D1 48
#define D2 48
#define D3 48
#define D4 24
#define NROW (D1*D2*D3)           // 110,592 x4-rows per channel
#define NSP  (D1*D2*D3*D4)        // 2,654,208 spatial points per channel
#define CN   (NC*NSP)             // 7,962,624 elems per batch image
#define NCOL (D1*D2)              // 2304 (x1,x2) columns
#define U2ROWS ((size_t)NCOL*64)  // rows per channel in 2-D transformed buf

// Scratch: batch-interleaved tensors, float2 = {b0, b1}
__device__ float2 s_fi[CN];
__device__ float2 s_bi[CN];
__device__ float2 s_g [CN];
__device__ float2 s_oA[CN];
__device__ float2 s_oB[CN];
// 2-D (x3,x4) Winograd-transformed inputs: [ci][col][x3t][p3] rows of 32 f2
__device__ float2 s_u2[6*U2ROWS*32];
// 2-D transformed Wg weights: [L][ci][k1k2 9][co 3][p3 8][p4 8] scalar
__device__ float s_w2d[LAYERS*6*9*3*64];

// A^T rows for F(6,3) inverse (matches validated R8/R9 inverse code)
__device__ const float A8T[48] = {
    1.f, 1.f,  1.f,  1.f,   1.f,  1.f,      1.f,      0.f,
    0.f, 1.f, -1.f,  2.f,  -2.f,  0.5f,    -0.5f,     0.f,
    0.f, 1.f,  1.f,  4.f,   4.f,  0.25f,    0.25f,    0.f,
    0.f, 1.f, -1.f,  8.f,  -8.f,  0.125f,  -0.125f,   0.f,
    0.f, 1.f,  1.f, 16.f,  16.f,  0.0625f,  0.0625f,  0.f,
    0.f, 1.f, -1.f, 32.f, -32.f,  0.03125f,-0.03125f, 1.f};

// ---- packed f32x2 ops ------------------------------------------------------
__device__ __forceinline__ float2 ffma2(float2 a, float2 b, float2 c) {
    unsigned long long ua, ub, uc, ud;
    ua = *reinterpret_cast<const unsigned long long*>(&a);
    ub = *reinterpret_cast<const unsigned long long*>(&b);
    uc = *reinterpret_cast<const unsigned long long*>(&c);
    asm("fma.rn.f32x2 %0, %1, %2, %3;" : "=l"(ud) : "l"(ua), "l"(ub), "l"(uc));
    return *reinterpret_cast<float2*>(&ud);
}
__device__ __forceinline__ float2 fadd2(float2 a, float2 b) {
    unsigned long long ua, ub, ud;
    ua = *reinterpret_cast<const unsigned long long*>(&a);
    ub = *reinterpret_cast<const unsigned long long*>(&b);
    asm("add.rn.f32x2 %0, %1, %2;" : "=l"(ud) : "l"(ua), "l"(ub));
    return *reinterpret_cast<float2*>(&ud);
}
__device__ __forceinline__ float2 fsub2(float2 a, float2 b) {
    return ffma2(b, make_float2(-1.f, -1.f), a);
}
__device__ __forceinline__ void cp_async16(void* smem, const void* gmem) {
    unsigned sa = (unsigned)__cvta_generic_to_shared(smem);
    asm volatile("cp.async.cg.shared.global [%0], [%1], 16;"
                 :: "r"(sa), "l"(gmem) : "memory");
}

// B^T (F(6,3)) — validated R8..R14
__device__ __forceinline__ void btrans8(const float2* x, float2* u) {
    const float2 z = make_float2(0.f, 0.f);
    u[0] = ffma2(fsub2(x[4], x[2]), make_float2(5.25f,5.25f), fsub2(x[0], x[6]));
    u[7] = ffma2(fsub2(x[3], x[5]), make_float2(5.25f,5.25f), fsub2(x[7], x[1]));
    {
        float2 e = ffma2(x[4], make_float2(-4.25f,-4.25f), fadd2(x[2], x[6]));
        float2 o = ffma2(x[3], make_float2(-4.25f,-4.25f), fadd2(x[1], x[5]));
        u[1] = fadd2(e, o);
        u[2] = fsub2(e, o);
    }
    {
        float2 e = ffma2(x[2], make_float2(0.25f,0.25f),
                   ffma2(x[4], make_float2(-1.25f,-1.25f), x[6]));
        float2 o = ffma2(x[1], make_float2(0.5f,0.5f),
                   ffma2(x[3], make_float2(-2.5f,-2.5f),
                   ffma2(x[5], make_float2(2.f,2.f), z)));
        u[3] = fadd2(e, o);
        u[4] = fsub2(e, o);
    }
    {
        float2 e = ffma2(x[2], make_float2(4.f,4.f),
                   ffma2(x[4], make_float2(-5.f,-5.f), x[6]));
        float2 o = ffma2(x[1], make_float2(2.f,2.f),
                   ffma2(x[3], make_float2(-2.5f,-2.5f),
                   ffma2(x[5], make_float2(0.5f,0.5f), z)));
        u[5] = fadd2(e, o);
        u[6] = fsub2(e, o);
    }
}

// ---------------------------------------------------------------------------
// Pack + 2-D Wg weight transform: W'[a][b] = sum G[a][k3] G[b][k4] w[k3][k4]
// ---------------------------------------------------------------------------
__global__ void pack_kernel(const float4* __restrict__ f,
                            const float4* __restrict__ bnd,
                            float4* __restrict__ fi,
                            float4* __restrict__ bi,
                            const float* __restrict__ Wg,
                            float* __restrict__ w2d) {
    int i = blockIdx.x * blockDim.x + threadIdx.x;
    if (i < LAYERS*6*9*3) {            // 648 weight-transform tasks
        int co = i % 3;  int r = i / 3;
        int k12 = r % 9; r /= 9;
        int ci = r % 6;  int L = r / 6;
        const float G[8][3] = {
            {1.f, 0.f, 0.f},
            {-2.f/9.f, -2.f/9.f, -2.f/9.f},
            {-2.f/9.f,  2.f/9.f, -2.f/9.f},
            {1.f/90.f,  1.f/45.f, 2.f/45.f},
            {1.f/90.f, -1.f/45.f, 2.f/45.f},
            {32.f/45.f, 16.f/45.f, 8.f/45.f},
            {32.f/45.f,-16.f/45.f, 8.f/45.f},
            {0.f, 0.f, 1.f}};
        const float* w = Wg + L*1458 + (co*6 + ci)*81 + k12*9;  // [k3][k4]
        float tmp[8][3];
        #pragma unroll
        for (int a = 0; a < 8; ++a)
            #pragma unroll
            for (int k4 = 0; k4 < 3; ++k4)
                tmp[a][k4] = G[a][0]*w[0*3 + k4] + G[a][1]*w[1*3 + k4]
                           + G[a][2]*w[2*3 + k4];
        float* o = w2d + (size_t)L*10368 + (((ci*9 + k12)*3 + co) * 64);
        #pragma unroll
        for (int a = 0; a < 8; ++a)
            #pragma unroll
            for (int b = 0; b < 8; ++b)
                o[a*8 + b] = G[b][0]*tmp[a][0] + G[b][1]*tmp[a][1]
                           + G[b][2]*tmp[a][2];
    }
    if (i >= CN / 4) return;
    float4 a = f[i],   b = f[i + CN / 4];
    fi[2*i]     = make_float4(a.x, b.x, a.y, b.y);
    fi[2*i + 1] = make_float4(a.z, b.z, a.w, b.w);
    a = bnd[i]; b = bnd[i + CN / 4];
    bi[2*i]     = make_float4(a.x, b.x, a.y, b.y);
    bi[2*i + 1] = make_float4(a.z, b.z, a.w, b.w);
}

// ---------------------------------------------------------------------------
// 2-D input transform (B^T along x4 then x3), one (ch, x1x2-column) per block.
// Output rows: [(ch*NCOL + col)*8 + x3t]*8 + p3, each 32 f2 (p4 points).
// ---------------------------------------------------------------------------
__global__ __launch_bounds__(256) void bx2_kernel(
    const float2* __restrict__ src, float2* __restrict__ dst)
{
    __shared__ float4 s1[48*13];     // raw column: 48 x3-rows x 12 f4 (+pad)
    __shared__ float4 s2[48*17];     // x4-transformed: 48 rows x 16 f4 (+pad)

    const int tid = threadIdx.x;
    const int col = blockIdx.x;      // x1*D2 + x2
    const int ch  = blockIdx.y;
    const float2 z = make_float2(0.f, 0.f);

    const float4* sp = (const float4*)(src + (size_t)ch*NSP) + (size_t)col*576;
    for (int idx = tid; idx < 576; idx += 256)
        s1[(idx/12)*13 + idx%12] = sp[idx];
    __syncthreads();

    if (tid < 192) {                 // x4 transform: 48 rows x 4 groups
        int r = tid >> 2, g = tid & 3;
        const float2* rp = (const float2*)&s1[r*13];
        float2 x[8];
        #pragma unroll
        for (int e = 0; e < 8; ++e) {
            int x4 = 6*g - 1 + e;
            x[e] = ((unsigned)x4 < (unsigned)D4) ? rp[x4] : z;
        }
        float2 u[8];
        btrans8(x, u);
        float4* o = &s2[r*17 + g*4];
        #pragma unroll
        for (int m = 0; m < 4; ++m)
            o[m] = make_float4(u[2*m].x, u[2*m].y, u[2*m+1].x, u[2*m+1].y);
    }
    __syncthreads();

    {                                // x3 transform: 8 x3t x 32 p4 columns
        int x3t = tid >> 5, c = tid & 31;
        const float2* s2f = (const float2*)s2;   // row stride 34 f2
        float2 x[8];
        #pragma unroll
        for (int e = 0; e < 8; ++e) {
            int x3 = 6*x3t - 1 + e;
            x[e] = ((unsigned)x3 < (unsigned)D3) ? s2f[x3*34 + c] : z;
        }
        float2 u[8];
        btrans8(x, u);
        size_t rb = ((size_t)(ch*NCOL + col)*8 + x3t)*8;
        #pragma unroll
        for (int p = 0; p < 8; ++p)
            dst[(rb + p)*32 + c] = u[p];
    }
}

// ---------------------------------------------------------------------------
// Wg conv in 2-D Winograd(x3,x4) domain. 512 threads, 1 block/SM.
// Tile x1=2, x2=8, x3tile=1 (6 x3), x4=24. Thread = (x1l, x2l, p3, q),
// acc[3co][8 p4]. Main loop: 6 ci x 9 k1k2 (k3,k4 eliminated).
// cp.async double-buffered input; weights reg-prefetched + STS per ci.
// ---------------------------------------------------------------------------
#define G2_BUF_F4 (320*17)                           // 5440 f4 per buffer
#define G2_W_F4   432                                // per-ci weights (f4)
#define G2_SMEM   ((2*G2_BUF_F4 + G2_W_F4)*16)       // 180,992 B

__global__ __launch_bounds__(512, 1) void wg2d_kernel(
    const float2* __restrict__ u2,
    const float*  __restrict__ wgt,   // this layer: [ci][k12][co][p3][p4]
    const float*  __restrict__ bias,
    float2* __restrict__ out)
{
    extern __shared__ float4 dsm4[];
    float4* buf0 = dsm4;
    float4* buf1 = dsm4 + G2_BUF_F4;
    float4* sW4  = dsm4 + 2*G2_BUF_F4;

    const int tid = threadIdx.x;
    const int q   = tid & 3;
    const int p3  = (tid >> 2) & 7;
    const int x2l = (tid >> 5) & 7;
    const int x1l = tid >> 8;
    const int x1g = blockIdx.x * 2;
    const int x2g = blockIdx.y * 8;
    const int x3t = blockIdx.z;

    auto stage = [&](int ci, float4* dst) {
        const float4* usrc = (const float4*)(u2 + (size_t)ci*U2ROWS*32);
        for (int idx = tid; idx < 320*16; idx += 512) {
            int r = idx >> 4, c = idx & 15;
            int pp = r & 7;  int t = r >> 3;
            int p2 = t % 10; int p1 = t / 10;
            int g1 = x1g - 1 + p1, g2 = x2g - 1 + p2;
            float4* d = dst + r*17 + c;
            if ((unsigned)g1 < (unsigned)D1 && (unsigned)g2 < (unsigned)D2)
                cp_async16(d, usrc +
                    ((size_t)(g1*D2 + g2)*64 + x3t*8 + pp)*16 + c);
            else
                *d = make_float4(0.f, 0.f, 0.f, 0.f);
        }
    };

    float2 acc[3][8];
    #pragma unroll
    for (int co = 0; co < 3; ++co)
        #pragma unroll
        for (int m = 0; m < 8; ++m) acc[co][m] = make_float2(0.f, 0.f);

    const float4* wsrc = (const float4*)wgt;
    float4 wr = make_float4(0.f, 0.f, 0.f, 0.f);
    if (tid < G2_W_F4) wr = wsrc[tid];          // weights ci=0

    stage(0, buf0);
    asm volatile("cp.async.commit_group;" ::: "memory");

    for (int ci = 0; ci < 6; ++ci) {
        if (ci + 1 < 6) {
            stage(ci + 1, (ci & 1) ? buf0 : buf1);
            asm volatile("cp.async.commit_group;" ::: "memory");
            asm volatile("cp.async.wait_group 1;" ::: "memory");
        } else {
            asm volatile("cp.async.wait_group 0;" ::: "memory");
        }
        __syncthreads();
        if (tid < G2_W_F4) {
            sW4[tid] = wr;                       // publish weights(ci)
            if (ci + 1 < 6) wr = wsrc[(ci + 1)*G2_W_F4 + tid];  // prefetch
        }
        __syncthreads();

        const float4* sIn = (ci & 1) ? buf1 : buf0;
        #pragma unroll
        for (int k12 = 0; k12 < 9; ++k12) {
            const int k1 = k12 / 3, k2 = k12 % 3;
            const float4* up = sIn
                + (((x1l + k1)*10 + (x2l + k2))*8 + p3)*17 + q*4;
            float4 ua[4];
            #pragma unroll
            for (int m = 0; m < 4; ++m) ua[m] = up[m];
            const float2* uf = reinterpret_cast<const float2*>(ua);

            #pragma unroll
            for (int co = 0; co < 3; ++co) {
                const float4* wp = sW4 + ((k12*3 + co)*8 + p3)*2;
                float4 wa = wp[0];
                float4 wb = wp[1];
                acc[co][0] = ffma2(uf[0], make_float2(wa.x,wa.x), acc[co][0]);
                acc[co][1] = ffma2(uf[1], make_float2(wa.y,wa.y), acc[co][1]);
                acc[co][2] = ffma2(uf[2], make_float2(wa.z,wa.z), acc[co][2]);
                acc[co][3] = ffma2(uf[3], make_float2(wa.w,wa.w), acc[co][3]);
                acc[co][4] = ffma2(uf[4], make_float2(wb.x,wb.x), acc[co][4]);
                acc[co][5] = ffma2(uf[5], make_float2(wb.y,wb.y), acc[co][5]);
                acc[co][6] = ffma2(uf[6], make_float2(wb.z,wb.z), acc[co][6]);
                acc[co][7] = ffma2(uf[7], make_float2(wb.w,wb.w), acc[co][7]);
            }
        }
        __syncthreads();
    }

    // ---- inverse: A^T along p4 (per thread), then A^T along p3 via smem ----
    float2* v = (float2*)dsm4;   // [co][x1l][x2l][p3][26], buffers now free
    #pragma unroll
    for (int co = 0; co < 3; ++co) {
        float2* m = acc[co];
        float2 s1 = fadd2(m[1], m[2]), d1 = fsub2(m[1], m[2]);
        float2 s3 = fadd2(m[3], m[4]), d3 = fsub2(m[3], m[4]);
        float2 s5 = fadd2(m[5], m[6]), d5 = fsub2(m[5], m[6]);
        float2 y[6];
        y[0] = fadd2(fadd2(m[0], s1), fadd2(s3, s5));
        y[1] = ffma2(d3, make_float2(2.f,2.f),
               ffma2(d5, make_float2(0.5f,0.5f), d1));
        y[2] = ffma2(s3, make_float2(4.f,4.f),
               ffma2(s5, make_float2(0.25f,0.25f), s1));
        y[3] = ffma2(d3, make_float2(8.f,8.f),
               ffma2(d5, make_float2(0.125f,0.125f), d1));
        y[4] = ffma2(s3, make_float2(16.f,16.f),
               ffma2(s5, make_float2(0.0625f,0.0625f), s1));
        y[5] = ffma2(d3, make_float2(32.f,32.f),
               ffma2(d5, make_float2(0.03125f,0.03125f), fadd2(d1, m[7])));
        float4* vp = (float4*)(v + ((((co*2 + x1l)*8 + x2l)*8 + p3)*26 + q*6));
        #pragma unroll
        for (int m2 = 0; m2 < 3; ++m2)
            vp[m2] = make_float4(y[2*m2].x, y[2*m2].y,
                                 y[2*m2+1].x, y[2*m2+1].y);
    }
    __syncthreads();

    const int ox3 = p3;
    if (ox3 < 6) {
        float av[8];
        #pragma unroll
        for (int p = 0; p < 8; ++p) av[p] = A8T[ox3*8 + p];

        const int x1 = x1g + x1l, x2 = x2g + x2l;
        const int base = ((x1*D2 + x2)*D3 + x3t*6 + ox3)*D4 + q*6;

        #pragma unroll
        for (int co = 0; co < 3; ++co) {
            float bsc = __ldg(bias + co);
            float2 y[6];
            #pragma unroll
            for (int j = 0; j < 6; ++j) y[j] = make_float2(bsc, bsc);
            #pragma unroll
            for (int p = 0; p < 8; ++p) {
                const float4* vp = (const float4*)
                    (v + ((((co*2 + x1l)*8 + x2l)*8 + p)*26 + q*6));
                float4 a0 = vp[0], a1 = vp[1], a2 = vp[2];
                float2 wv = make_float2(av[p], av[p]);
                y[0] = ffma2(make_float2(a0.x, a0.y), wv, y[0]);
                y[1] = ffma2(make_float2(a0.z, a0.w), wv, y[1]);
                y[2] = ffma2(make_float2(a1.x, a1.y), wv, y[2]);
                y[3] = ffma2(make_float2(a1.z, a1.w), wv, y[3]);
                y[4] = ffma2(make_float2(a2.x, a2.y), wv, y[4]);
                y[5] = ffma2(make_float2(a2.z, a2.w), wv, y[5]);
            }
            float4* op = (float4*)(out + (size_t)co*NSP + base);
            #pragma unroll
            for (int m2 = 0; m2 < 3; ++m2)
                op[m2] = make_float4(y[2*m2].x, y[2*m2].y,
                                     y[2*m2+1].x, y[2*m2+1].y);
        }
    }
}

// ---------------------------------------------------------------------------
// Fused W1 + W2/Wd epilogue (w1f) — R14-validated, minus the B^T tail
// (u2 for the next layer is produced by bx2 instead).
// ---------------------------------------------------------------------------
#define W1_BUF_F4 (240*13)
#define W1_SMEM   (324*8 + 2*W1_BUF_F4*16)          // 102,432 B

__global__ __launch_bounds__(256, 2) void w1f_kernel(
    const float2* __restrict__ g,   const float2* __restrict__ cur,
    const float*  __restrict__ W1w, const float* __restrict__ b1,
    const float*  __restrict__ W2w, const float* __restrict__ b2,
    const float*  __restrict__ Wdw, const float* __restrict__ bd,
    float2* __restrict__ onew, float* __restrict__ ofinal, int final_layer)
{
    extern __shared__ float2 dsm[];
    float2* sW   = dsm;
    float4* buf0 = (float4*)(dsm + 324);
    float4* buf1 = buf0 + W1_BUF_F4;

    const int tid = threadIdx.x;
    const int x3l = tid & 7;
    const int q   = (tid >> 3) & 3;
    const int x2l = (tid >> 5) & 3;
    const int x1l = tid >> 7;
    const int x1g = blockIdx.x * 2;
    const int x2g = blockIdx.y * 4;
    const int x3g = blockIdx.z * 8;
    const float2 z = make_float2(0.f, 0.f);

    for (int s = tid; s < 81*3; s += 256) {
        int grp = s / 3, co = s % 3;
        int ci = grp / 27, k = grp % 27;
        float w = W1w[(co*3 + ci)*27 + k];
        sW[grp*4 + co] = make_float2(w, w);
    }

    auto stage = [&](int ci, float4* dst) {
        const float4* src = (const float4*)(g + (size_t)ci*NSP);
        for (int idx = tid; idx < 240*12; idx += 256) {
            int row = idx / 12, c = idx % 12;
            int p3 = row % 10; int t = row / 10; int p2 = t % 6; int p1 = t / 6;
            int g1 = x1g - 1 + p1, g2 = x2g - 1 + p2, g3 = x3g - 1 + p3;
            float4* d = dst + row*13 + c;
            if ((unsigned)g1 < (unsigned)D1 && (unsigned)g2 < (unsigned)D2 &&
                (unsigned)g3 < (unsigned)D3)
                cp_async16(d, src + (size_t)((g1*D2 + g2)*D3 + g3)*12 + c);
            else
                *d = make_float4(0.f, 0.f, 0.f, 0.f);
        }
    };

    float2 acc[3][6];
    #pragma unroll
    for (int co = 0; co < 3; ++co) {
        float b = __ldg(b1 + co);
        #pragma unroll
        for (int j = 0; j < 6; ++j) acc[co][j] = make_float2(b, b);
    }

    stage(0, buf0);
    asm volatile("cp.async.commit_group;" ::: "memory");

    for (int ci = 0; ci < 3; ++ci) {
        if (ci + 1 < 3) {
            stage(ci + 1, (ci & 1) ? buf0 : buf1);
            asm volatile("cp.async.commit_group;" ::: "memory");
            asm volatile("cp.async.wait_group 1;" ::: "memory");
        } else {
            asm volatile("cp.async.wait_group 0;" ::: "memory");
        }
        __syncthreads();

        const float4* sIn = (ci & 1) ? buf1 : buf0;
        const float2* wci = sW + ci * 108;
        #pragma unroll 1
        for (int k1 = 0; k1 < 3; ++k1) {
            #pragma unroll
            for (int k23 = 0; k23 < 9; ++k23) {
                const int k2 = k23 / 3, k3 = k23 % 3;
                const float4* ip = sIn
                    + (((x1l + k1)*6 + (x2l + k2))*10 + (x3l + k3))*13 + q*3;
                float4 a4[3];
                #pragma unroll
                for (int m = 0; m < 3; ++m) a4[m] = ip[m];
                const float2* uf = reinterpret_cast<const float2*>(a4);

                const float2* wp = wci + (k1*9 + k23)*4;
                float2 w0 = wp[0];
                float2 w1 = wp[1];
                float2 w2 = wp[2];
                #pragma unroll
                for (int j = 0; j < 6; ++j) {
                    acc[0][j] = ffma2(uf[j], w0, acc[0][j]);
                    acc[1][j] = ffma2(uf[j], w1, acc[1][j]);
                    acc[2][j] = ffma2(uf[j], w2, acc[2][j]);
                }
            }
        }
        __syncthreads();
    }

    const int x1 = x1g + x1l, x2 = x2g + x2l, x3 = x3g + x3l;
    const size_t row = (size_t)((x1*D2 + x2)*D3 + x3);
    const size_t base = row*D4 + q*6;

    float2 tlo[3], thi[3];
    #pragma unroll
    for (int c = 0; c < 3; ++c) {
        float lx = __shfl_up_sync(0xffffffffu,   acc[c][5].x, 8);
        float ly = __shfl_up_sync(0xffffffffu,   acc[c][5].y, 8);
        float hx = __shfl_down_sync(0xffffffffu, acc[c][0].x, 8);
        float hy = __shfl_down_sync(0xffffffffu, acc[c][0].y, 8);
        tlo[c] = (q > 0) ? make_float2(lx, ly) : z;
        thi[c] = (q < 3) ? make_float2(hx, hy) : z;
    }

    float2 r12[3][6];
    #pragma unroll
    for (int co = 0; co < 3; ++co) {
        float b = __ldg(b2 + co) + __ldg(bd + co);
        #pragma unroll
        for (int j = 0; j < 6; ++j) r12[co][j] = make_float2(b, b);
    }

    #pragma unroll
    for (int ci = 0; ci < 3; ++ci) {
        float2 tv[8];
        tv[0] = tlo[ci];
        #pragma unroll
        for (int j = 0; j < 6; ++j) tv[j + 1] = acc[ci][j];
        tv[7] = thi[ci];

        const float4* cp = (const float4*)(cur + (size_t)ci*NSP + row*D4) + q*3;
        float4 c4[3];
        #pragma unroll
        for (int m = 0; m < 3; ++m) c4[m] = cp[m];
        const float2* cf = reinterpret_cast<const float2*>(c4);

        #pragma unroll
        for (int co = 0; co < 3; ++co) {
            float w0s = __ldg(W2w + (co*3 + ci)*3 + 0);
            float w1s = __ldg(W2w + (co*3 + ci)*3 + 1);
            float w2s = __ldg(W2w + (co*3 + ci)*3 + 2);
            float wds = __ldg(Wdw + co*3 + ci);
            float2 w0 = make_float2(w0s, w0s);
            float2 w1 = make_float2(w1s, w1s);
            float2 w2 = make_float2(w2s, w2s);
            float2 wd = make_float2(wds, wds);
            #pragma unroll
            for (int j = 0; j < 6; ++j) {
                float2 a = r12[co][j];
                a = ffma2(tv[j],     w0, a);
                a = ffma2(tv[j + 1], w1, a);
                a = ffma2(tv[j + 2], w2, a);
                a = ffma2(cf[j],     wd, a);
                r12[co][j] = a;
            }
        }
    }

    if (final_layer) {
        #pragma unroll
        for (int co = 0; co < 3; ++co) {
            float2* o0 = (float2*)(ofinal + (size_t)co*NSP + base);
            float2* o1 = (float2*)(ofinal + CN + (size_t)co*NSP + base);
            #pragma unroll
            for (int m = 0; m < 3; ++m) {
                o0[m] = make_float2(r12[co][2*m].x, r12[co][2*m + 1].x);
                o1[m] = make_float2(r12[co][2*m].y, r12[co][2*m + 1].y);
            }
        }
        return;
    }

    #pragma unroll
    for (int co = 0; co < 3; ++co) {
        float4* op = (float4*)(onew + (size_t)co*NSP + row*D4) + q*3;
        #pragma unroll
        for (int m = 0; m < 3; ++m)
            op[m] = make_float4(r12[co][2*m].x,   r12[co][2*m].y,
                                r12[co][2*m+1].x, r12[co][2*m+1].y);
    }
}

// ---------------------------------------------------------------------------
// Driver
// ---------------------------------------------------------------------------
extern "C" void kernel_launch(void* const* d_in, const int* in_sizes, int n_in,
                              void* d_out, int out_size)
{
    const float* f   = (const float*)d_in[0];
    const float* bnd = (const float*)d_in[1];
    const float* Wg  = (const float*)d_in[2];
    const float* bg  = (const float*)d_in[3];
    const float* W1  = (const float*)d_in[4];
    const float* b1  = (const float*)d_in[5];
    const float* W2  = (const float*)d_in[6];
    const float* b2  = (const float*)d_in[7];
    const float* Wd  = (const float*)d_in[8];
    const float* bd  = (const float*)d_in[9];

    static bool attr_done = false;
    if (!attr_done) {
        cudaFuncSetAttribute(wg2d_kernel,
            cudaFuncAttributeMaxDynamicSharedMemorySize, G2_SMEM);
        cudaFuncSetAttribute(w1f_kernel,
            cudaFuncAttributeMaxDynamicSharedMemorySize, W1_SMEM);
        attr_done = true;
    }

    float2 *fi, *bi, *gg, *oA, *oB, *ub;
    float *w2d;
    cudaGetSymbolAddress((void**)&fi, s_fi);
    cudaGetSymbolAddress((void**)&bi, s_bi);
    cudaGetSymbolAddress((void**)&gg, s_g);
    cudaGetSymbolAddress((void**)&oA, s_oA);
    cudaGetSymbolAddress((void**)&oB, s_oB);
    cudaGetSymbolAddress((void**)&ub, s_u2);
    cudaGetSymbolAddress((void**)&w2d, s_w2d);

    pack_kernel<<<(CN/4 + 255) / 256, 256>>>(
        (const float4*)f, (const float4*)bnd, (float4*)fi, (float4*)bi,
        Wg, w2d);

    // one-time 2-D transforms: f -> u2[0..2], boundary -> u2[3..5]
    bx2_kernel<<<dim3(NCOL, 3), 256>>>(fi, ub);
    bx2_kernel<<<dim3(NCOL, 3), 256>>>(bi, ub + 3*U2ROWS*32);
    // launch order: harness(2) + pack + 2x bx2 => first wg2d in ncu -s 5 slot

    dim3 ggrid(D1/2, D2/8, D3/6);      // 24 x 6 x 8 = 1152 blocks
    dim3 cgrid(D1/2, D2/4, D3/8);      // w1f
    const float2* cur = fi;
    float2* outs[LAYERS] = {oA, oB, oA, nullptr};

    for (int i = 0; i < LAYERS; ++i) {
        wg2d_kernel<<<ggrid, 512, G2_SMEM>>>(
            ub, w2d + (size_t)i*10368, bg + i*3, gg);
        w1f_kernel<<<cgrid, 256, W1_SMEM>>>(
            gg, cur, W1 + i*243, b1 + i*3, W2 + i*27, b2 + i*3,
            Wd + i*9, bd + i*3,
            outs[i], (float*)d_out, (i == LAYERS - 1) ? 1 : 0);
        if (i < LAYERS - 1)
            bx2_kernel<<<dim3(NCOL, 3), 256>>>(outs[i], ub);
        cur = outs[i];
    }
}

// round 17
// speedup vs baseline: 2.4673x; 1.0244x over previous
#include <cuda_runtime.h>
#include <cuda_bf16.h>

// ---------------------------------------------------------------------------
// Problem constants
// ---------------------------------------------------------------------------
#define LAYERS 4
#define NC 3
#define D1 48
#define D2 48
#define D3 48
#define D4 24
#define NROW (D1*D2*D3)           // 110,592 x4-rows per channel
#define NSP  (D1*D2*D3*D4)        // 2,654,208 spatial points per channel
#define CN   (NC*NSP)             // 7,962,624 elems per batch image
#define NCOL (D1*D2)              // 2304 (x1,x2) columns
#define U2ROWS ((size_t)NCOL*64)  // rows per channel in 2-D transformed buf

// Scratch: batch-interleaved tensors, float2 = {b0, b1}
__device__ float2 s_fi[CN];
__device__ float2 s_bi[CN];
__device__ float2 s_g [CN];
__device__ float2 s_oA[CN];
__device__ float2 s_oB[CN];
// 2-D (x3,x4) Winograd-transformed inputs: [ci][col][x3t][p3] rows of 32 f2
__device__ float2 s_u2[6*U2ROWS*32];
// 2-D transformed Wg weights: [L][ci][k1k2 9][co 3][p3 8][p4 8] scalar
__device__ float s_w2d[LAYERS*6*9*3*64];

// A^T rows for F(6,3) inverse (matches validated R8/R9 inverse code)
__device__ const float A8T[48] = {
    1.f, 1.f,  1.f,  1.f,   1.f,  1.f,      1.f,      0.f,
    0.f, 1.f, -1.f,  2.f,  -2.f,  0.5f,    -0.5f,     0.f,
    0.f, 1.f,  1.f,  4.f,   4.f,  0.25f,    0.25f,    0.f,
    0.f, 1.f, -1.f,  8.f,  -8.f,  0.125f,  -0.125f,   0.f,
    0.f, 1.f,  1.f, 16.f,  16.f,  0.0625f,  0.0625f,  0.f,
    0.f, 1.f, -1.f, 32.f, -32.f,  0.03125f,-0.03125f, 1.f};

// ---- packed f32x2 ops ------------------------------------------------------
__device__ __forceinline__ float2 ffma2(float2 a, float2 b, float2 c) {
    unsigned long long ua, ub, uc, ud;
    ua = *reinterpret_cast<const unsigned long long*>(&a);
    ub = *reinterpret_cast<const unsigned long long*>(&b);
    uc = *reinterpret_cast<const unsigned long long*>(&c);
    asm("fma.rn.f32x2 %0, %1, %2, %3;" : "=l"(ud) : "l"(ua), "l"(ub), "l"(uc));
    return *reinterpret_cast<float2*>(&ud);
}
__device__ __forceinline__ float2 fadd2(float2 a, float2 b) {
    unsigned long long ua, ub, ud;
    ua = *reinterpret_cast<const unsigned long long*>(&a);
    ub = *reinterpret_cast<const unsigned long long*>(&b);
    asm("add.rn.f32x2 %0, %1, %2;" : "=l"(ud) : "l"(ua), "l"(ub));
    return *reinterpret_cast<float2*>(&ud);
}
__device__ __forceinline__ float2 fsub2(float2 a, float2 b) {
    return ffma2(b, make_float2(-1.f, -1.f), a);
}
__device__ __forceinline__ void cp_async16(void* smem, const void* gmem) {
    unsigned sa = (unsigned)__cvta_generic_to_shared(smem);
    asm volatile("cp.async.cg.shared.global [%0], [%1], 16;"
                 :: "r"(sa), "l"(gmem) : "memory");
}

// B^T (F(6,3)) — validated R8..R15
__device__ __forceinline__ void btrans8(const float2* x, float2* u) {
    const float2 z = make_float2(0.f, 0.f);
    u[0] = ffma2(fsub2(x[4], x[2]), make_float2(5.25f,5.25f), fsub2(x[0], x[6]));
    u[7] = ffma2(fsub2(x[3], x[5]), make_float2(5.25f,5.25f), fsub2(x[7], x[1]));
    {
        float2 e = ffma2(x[4], make_float2(-4.25f,-4.25f), fadd2(x[2], x[6]));
        float2 o = ffma2(x[3], make_float2(-4.25f,-4.25f), fadd2(x[1], x[5]));
        u[1] = fadd2(e, o);
        u[2] = fsub2(e, o);
    }
    {
        float2 e = ffma2(x[2], make_float2(0.25f,0.25f),
                   ffma2(x[4], make_float2(-1.25f,-1.25f), x[6]));
        float2 o = ffma2(x[1], make_float2(0.5f,0.5f),
                   ffma2(x[3], make_float2(-2.5f,-2.5f),
                   ffma2(x[5], make_float2(2.f,2.f), z)));
        u[3] = fadd2(e, o);
        u[4] = fsub2(e, o);
    }
    {
        float2 e = ffma2(x[2], make_float2(4.f,4.f),
                   ffma2(x[4], make_float2(-5.f,-5.f), x[6]));
        float2 o = ffma2(x[1], make_float2(2.f,2.f),
                   ffma2(x[3], make_float2(-2.5f,-2.5f),
                   ffma2(x[5], make_float2(0.5f,0.5f), z)));
        u[5] = fadd2(e, o);
        u[6] = fsub2(e, o);
    }
}

// ---------------------------------------------------------------------------
// Pack + 2-D Wg weight transform   [UNCHANGED — R15 passing]
// ---------------------------------------------------------------------------
__global__ void pack_kernel(const float4* __restrict__ f,
                            const float4* __restrict__ bnd,
                            float4* __restrict__ fi,
                            float4* __restrict__ bi,
                            const float* __restrict__ Wg,
                            float* __restrict__ w2d) {
    int i = blockIdx.x * blockDim.x + threadIdx.x;
    if (i < LAYERS*6*9*3) {
        int co = i % 3;  int r = i / 3;
        int k12 = r % 9; r /= 9;
        int ci = r % 6;  int L = r / 6;
        const float G[8][3] = {
            {1.f, 0.f, 0.f},
            {-2.f/9.f, -2.f/9.f, -2.f/9.f},
            {-2.f/9.f,  2.f/9.f, -2.f/9.f},
            {1.f/90.f,  1.f/45.f, 2.f/45.f},
            {1.f/90.f, -1.f/45.f, 2.f/45.f},
            {32.f/45.f, 16.f/45.f, 8.f/45.f},
            {32.f/45.f,-16.f/45.f, 8.f/45.f},
            {0.f, 0.f, 1.f}};
        const float* w = Wg + L*1458 + (co*6 + ci)*81 + k12*9;
        float tmp[8][3];
        #pragma unroll
        for (int a = 0; a < 8; ++a)
            #pragma unroll
            for (int k4 = 0; k4 < 3; ++k4)
                tmp[a][k4] = G[a][0]*w[0*3 + k4] + G[a][1]*w[1*3 + k4]
                           + G[a][2]*w[2*3 + k4];
        float* o = w2d + (size_t)L*10368 + (((ci*9 + k12)*3 + co) * 64);
        #pragma unroll
        for (int a = 0; a < 8; ++a)
            #pragma unroll
            for (int b = 0; b < 8; ++b)
                o[a*8 + b] = G[b][0]*tmp[a][0] + G[b][1]*tmp[a][1]
                           + G[b][2]*tmp[a][2];
    }
    if (i >= CN / 4) return;
    float4 a = f[i],   b = f[i + CN / 4];
    fi[2*i]     = make_float4(a.x, b.x, a.y, b.y);
    fi[2*i + 1] = make_float4(a.z, b.z, a.w, b.w);
    a = bnd[i]; b = bnd[i + CN / 4];
    bi[2*i]     = make_float4(a.x, b.x, a.y, b.y);
    bi[2*i + 1] = make_float4(a.z, b.z, a.w, b.w);
}

// ---------------------------------------------------------------------------
// 2-D input transform (B^T along x4 then x3)   [UNCHANGED — R15 passing]
// ---------------------------------------------------------------------------
__global__ __launch_bounds__(256) void bx2_kernel(
    const float2* __restrict__ src, float2* __restrict__ dst)
{
    __shared__ float4 s1[48*13];
    __shared__ float4 s2[48*17];

    const int tid = threadIdx.x;
    const int col = blockIdx.x;
    const int ch  = blockIdx.y;
    const float2 z = make_float2(0.f, 0.f);

    const float4* sp = (const float4*)(src + (size_t)ch*NSP) + (size_t)col*576;
    for (int idx = tid; idx < 576; idx += 256)
        s1[(idx/12)*13 + idx%12] = sp[idx];
    __syncthreads();

    if (tid < 192) {
        int r = tid >> 2, g = tid & 3;
        const float2* rp = (const float2*)&s1[r*13];
        float2 x[8];
        #pragma unroll
        for (int e = 0; e < 8; ++e) {
            int x4 = 6*g - 1 + e;
            x[e] = ((unsigned)x4 < (unsigned)D4) ? rp[x4] : z;
        }
        float2 u[8];
        btrans8(x, u);
        float4* o = &s2[r*17 + g*4];
        #pragma unroll
        for (int m = 0; m < 4; ++m)
            o[m] = make_float4(u[2*m].x, u[2*m].y, u[2*m+1].x, u[2*m+1].y);
    }
    __syncthreads();

    {
        int x3t = tid >> 5, c = tid & 31;
        const float2* s2f = (const float2*)s2;
        float2 x[8];
        #pragma unroll
        for (int e = 0; e < 8; ++e) {
            int x3 = 6*x3t - 1 + e;
            x[e] = ((unsigned)x3 < (unsigned)D3) ? s2f[x3*34 + c] : z;
        }
        float2 u[8];
        btrans8(x, u);
        size_t rb = ((size_t)(ch*NCOL + col)*8 + x3t)*8;
        #pragma unroll
        for (int p = 0; p < 8; ++p)
            dst[(rb + p)*32 + c] = u[p];
    }
}

// ---------------------------------------------------------------------------
// Wg conv in 2-D Winograd(x3,x4) domain — R16 structure with the staging
// offset bug FIXED: row index must be scaled by 16 f4/row (*1024, not *64).
// ---------------------------------------------------------------------------
#define G2_BUF_F4 (320*17)                           // 5440 f4 per buffer
#define G2_W_F4   432                                // per-ci weights (f4)
#define G2_SMEM   ((2*G2_BUF_F4 + 6*G2_W_F4)*16)     // 215,552 B

__global__ __launch_bounds__(512, 1) void wg2d_kernel(
    const float2* __restrict__ u2,
    const float*  __restrict__ wgt,   // this layer: [ci][k12][co][p3][p4]
    const float*  __restrict__ bias,
    float2* __restrict__ out)
{
    extern __shared__ float4 dsm4[];
    float4* buf0 = dsm4;
    float4* buf1 = dsm4 + G2_BUF_F4;
    float4* sW4  = dsm4 + 2*G2_BUF_F4;   // [ci][k12][co][p3][2]

    const int tid = threadIdx.x;
    const int q   = tid & 3;
    const int p3  = (tid >> 2) & 7;
    const int x2l = (tid >> 5) & 7;
    const int x1l = tid >> 8;
    const int x1g = blockIdx.x * 2;
    const int x2g = blockIdx.y * 8;
    const int x3t = blockIdx.z;

    // staging: thread-invariant decomposition (verified == R15 div/mod walk)
    const int sc  = tid & 15;            // f4 column
    const int spp = (tid >> 4) & 7;      // p3 within row group (step 32 rows)
    const int st0 = tid >> 7;            // initial t (0..3)

    auto stage = [&](int ci, float4* dst) {
        const float4* usrc = (const float4*)(u2 + (size_t)ci*U2ROWS*32)
                             + (size_t)(x3t*8 + spp)*16 + sc;
        float4* d = dst + ((st0*8 + spp)*17 + sc);
        int p1 = 0, p2 = st0;
        #pragma unroll
        for (int k = 0; k < 10; ++k) {
            int g1 = x1g - 1 + p1, g2 = x2g - 1 + p2;
            if ((unsigned)g1 < (unsigned)D1 && (unsigned)g2 < (unsigned)D2)
                cp_async16(d, usrc + (size_t)(g1*D2 + g2)*1024);  // 64 rows * 16 f4
            else
                *d = make_float4(0.f, 0.f, 0.f, 0.f);
            d += 32*17;                   // row += 32
            p2 += 4; if (p2 >= 10) { p2 -= 10; ++p1; }
        }
    };

    float2 acc[3][8];
    #pragma unroll
    for (int co = 0; co < 3; ++co)
        #pragma unroll
        for (int m = 0; m < 8; ++m) acc[co][m] = make_float2(0.f, 0.f);

    // group 0: input ci=0 + ALL weights
    stage(0, buf0);
    {
        const float4* wsrc = (const float4*)wgt;
        for (int s = tid; s < 6*G2_W_F4; s += 512)
            cp_async16(sW4 + s, wsrc + s);
    }
    asm volatile("cp.async.commit_group;" ::: "memory");

    for (int ci = 0; ci < 6; ++ci) {
        if (ci + 1 < 6) {
            stage(ci + 1, (ci & 1) ? buf0 : buf1);
            asm volatile("cp.async.commit_group;" ::: "memory");
            asm volatile("cp.async.wait_group 1;" ::: "memory");
        } else {
            asm volatile("cp.async.wait_group 0;" ::: "memory");
        }
        __syncthreads();

        const float4* sIn = (ci & 1) ? buf1 : buf0;
        const float4* sWc = sW4 + ci*G2_W_F4;
        #pragma unroll
        for (int k12 = 0; k12 < 9; ++k12) {
            const int k1 = k12 / 3, k2 = k12 % 3;
            const float4* up = sIn
                + (((x1l + k1)*10 + (x2l + k2))*8 + p3)*17 + q*4;
            float4 ua[4];
            #pragma unroll
            for (int m = 0; m < 4; ++m) ua[m] = up[m];
            const float2* uf = reinterpret_cast<const float2*>(ua);

            #pragma unroll
            for (int co = 0; co < 3; ++co) {
                const float4* wp = sWc + ((k12*3 + co)*8 + p3)*2;
                float4 wa = wp[0];
                float4 wb = wp[1];
                acc[co][0] = ffma2(uf[0], make_float2(wa.x,wa.x), acc[co][0]);
                acc[co][1] = ffma2(uf[1], make_float2(wa.y,wa.y), acc[co][1]);
                acc[co][2] = ffma2(uf[2], make_float2(wa.z,wa.z), acc[co][2]);
                acc[co][3] = ffma2(uf[3], make_float2(wa.w,wa.w), acc[co][3]);
                acc[co][4] = ffma2(uf[4], make_float2(wb.x,wb.x), acc[co][4]);
                acc[co][5] = ffma2(uf[5], make_float2(wb.y,wb.y), acc[co][5]);
                acc[co][6] = ffma2(uf[6], make_float2(wb.z,wb.z), acc[co][6]);
                acc[co][7] = ffma2(uf[7], make_float2(wb.w,wb.w), acc[co][7]);
            }
        }
        __syncthreads();
    }

    // ---- inverse: A^T along p4 (per thread), then A^T along p3 via smem ----
    float2* v = (float2*)dsm4;   // buffers now free (sW4 region untouched)
    #pragma unroll
    for (int co = 0; co < 3; ++co) {
        float2* m = acc[co];
        float2 s1 = fadd2(m[1], m[2]), d1 = fsub2(m[1], m[2]);
        float2 s3 = fadd2(m[3], m[4]), d3 = fsub2(m[3], m[4]);
        float2 s5 = fadd2(m[5], m[6]), d5 = fsub2(m[5], m[6]);
        float2 y[6];
        y[0] = fadd2(fadd2(m[0], s1), fadd2(s3, s5));
        y[1] = ffma2(d3, make_float2(2.f,2.f),
               ffma2(d5, make_float2(0.5f,0.5f), d1));
        y[2] = ffma2(s3, make_float2(4.f,4.f),
               ffma2(s5, make_float2(0.25f,0.25f), s1));
        y[3] = ffma2(d3, make_float2(8.f,8.f),
               ffma2(d5, make_float2(0.125f,0.125f), d1));
        y[4] = ffma2(s3, make_float2(16.f,16.f),
               ffma2(s5, make_float2(0.0625f,0.0625f), s1));
        y[5] = ffma2(d3, make_float2(32.f,32.f),
               ffma2(d5, make_float2(0.03125f,0.03125f), fadd2(d1, m[7])));
        float4* vp = (float4*)(v + ((((co*2 + x1l)*8 + x2l)*8 + p3)*26 + q*6));
        #pragma unroll
        for (int m2 = 0; m2 < 3; ++m2)
            vp[m2] = make_float4(y[2*m2].x, y[2*m2].y,
                                 y[2*m2+1].x, y[2*m2+1].y);
    }
    __syncthreads();

    const int ox3 = p3;
    if (ox3 < 6) {
        float av[8];
        #pragma unroll
        for (int p = 0; p < 8; ++p) av[p] = A8T[ox3*8 + p];

        const int x1 = x1g + x1l, x2 = x2g + x2l;
        const int base = ((x1*D2 + x2)*D3 + x3t*6 + ox3)*D4 + q*6;

        #pragma unroll
        for (int co = 0; co < 3; ++co) {
            float bsc = __ldg(bias + co);
            float2 y[6];
            #pragma unroll
            for (int j = 0; j < 6; ++j) y[j] = make_float2(bsc, bsc);
            #pragma unroll
            for (int p = 0; p < 8; ++p) {
                const float4* vp = (const float4*)
                    (v + ((((co*2 + x1l)*8 + x2l)*8 + p)*26 + q*6));
                float4 a0 = vp[0], a1 = vp[1], a2 = vp[2];
                float2 wv = make_float2(av[p], av[p]);
                y[0] = ffma2(make_float2(a0.x, a0.y), wv, y[0]);
                y[1] = ffma2(make_float2(a0.z, a0.w), wv, y[1]);
                y[2] = ffma2(make_float2(a1.x, a1.y), wv, y[2]);
                y[3] = ffma2(make_float2(a1.z, a1.w), wv, y[3]);
                y[4] = ffma2(make_float2(a2.x, a2.y), wv, y[4]);
                y[5] = ffma2(make_float2(a2.z, a2.w), wv, y[5]);
            }
            float4* op = (float4*)(out + (size_t)co*NSP + base);
            #pragma unroll
            for (int m2 = 0; m2 < 3; ++m2)
                op[m2] = make_float4(y[2*m2].x, y[2*m2].y,
                                     y[2*m2+1].x, y[2*m2+1].y);
        }
    }
}

// ---------------------------------------------------------------------------
// Fused W1 + W2/Wd epilogue (w1f)   [UNCHANGED — R14/R15 passing]
// ---------------------------------------------------------------------------
#define W1_BUF_F4 (240*13)
#define W1_SMEM   (324*8 + 2*W1_BUF_F4*16)          // 102,432 B

__global__ __launch_bounds__(256, 2) void w1f_kernel(
    const float2* __restrict__ g,   const float2* __restrict__ cur,
    const float*  __restrict__ W1w, const float* __restrict__ b1,
    const float*  __restrict__ W2w, const float* __restrict__ b2,
    const float*  __restrict__ Wdw, const float* __restrict__ bd,
    float2* __restrict__ onew, float* __restrict__ ofinal, int final_layer)
{
    extern __shared__ float2 dsm[];
    float2* sW   = dsm;
    float4* buf0 = (float4*)(dsm + 324);
    float4* buf1 = buf0 + W1_BUF_F4;

    const int tid = threadIdx.x;
    const int x3l = tid & 7;
    const int q   = (tid >> 3) & 3;
    const int x2l = (tid >> 5) & 3;
    const int x1l = tid >> 7;
    const int x1g = blockIdx.x * 2;
    const int x2g = blockIdx.y * 4;
    const int x3g = blockIdx.z * 8;
    const float2 z = make_float2(0.f, 0.f);

    for (int s = tid; s < 81*3; s += 256) {
        int grp = s / 3, co = s % 3;
        int ci = grp / 27, k = grp % 27;
        float w = W1w[(co*3 + ci)*27 + k];
        sW[grp*4 + co] = make_float2(w, w);
    }

    auto stage = [&](int ci, float4* dst) {
        const float4* src = (const float4*)(g + (size_t)ci*NSP);
        for (int idx = tid; idx < 240*12; idx += 256) {
            int row = idx / 12, c = idx % 12;
            int p3 = row % 10; int t = row / 10; int p2 = t % 6; int p1 = t / 6;
            int g1 = x1g - 1 + p1, g2 = x2g - 1 + p2, g3 = x3g - 1 + p3;
            float4* d = dst + row*13 + c;
            if ((unsigned)g1 < (unsigned)D1 && (unsigned)g2 < (unsigned)D2 &&
                (unsigned)g3 < (unsigned)D3)
                cp_async16(d, src + (size_t)((g1*D2 + g2)*D3 + g3)*12 + c);
            else
                *d = make_float4(0.f, 0.f, 0.f, 0.f);
        }
    };

    float2 acc[3][6];
    #pragma unroll
    for (int co = 0; co < 3; ++co) {
        float b = __ldg(b1 + co);
        #pragma unroll
        for (int j = 0; j < 6; ++j) acc[co][j] = make_float2(b, b);
    }

    stage(0, buf0);
    asm volatile("cp.async.commit_group;" ::: "memory");

    for (int ci = 0; ci < 3; ++ci) {
        if (ci + 1 < 3) {
            stage(ci + 1, (ci & 1) ? buf0 : buf1);
            asm volatile("cp.async.commit_group;" ::: "memory");
            asm volatile("cp.async.wait_group 1;" ::: "memory");
        } else {
            asm volatile("cp.async.wait_group 0;" ::: "memory");
        }
        __syncthreads();

        const float4* sIn = (ci & 1) ? buf1 : buf0;
        const float2* wci = sW + ci * 108;
        #pragma unroll 1
        for (int k1 = 0; k1 < 3; ++k1) {
            #pragma unroll
            for (int k23 = 0; k23 < 9; ++k23) {
                const int k2 = k23 / 3, k3 = k23 % 3;
                const float4* ip = sIn
                    + (((x1l + k1)*6 + (x2l + k2))*10 + (x3l + k3))*13 + q*3;
                float4 a4[3];
                #pragma unroll
                for (int m = 0; m < 3; ++m) a4[m] = ip[m];
                const float2* uf = reinterpret_cast<const float2*>(a4);

                const float2* wp = wci + (k1*9 + k23)*4;
                float2 w0 = wp[0];
                float2 w1 = wp[1];
                float2 w2 = wp[2];
                #pragma unroll
                for (int j = 0; j < 6; ++j) {
                    acc[0][j] = ffma2(uf[j], w0, acc[0][j]);
                    acc[1][j] = ffma2(uf[j], w1, acc[1][j]);
                    acc[2][j] = ffma2(uf[j], w2, acc[2][j]);
                }
            }
        }
        __syncthreads();
    }

    const int x1 = x1g + x1l, x2 = x2g + x2l, x3 = x3g + x3l;
    const size_t row = (size_t)((x1*D2 + x2)*D3 + x3);
    const size_t base = row*D4 + q*6;

    float2 tlo[3], thi[3];
    #pragma unroll
    for (int c = 0; c < 3; ++c) {
        float lx = __shfl_up_sync(0xffffffffu,   acc[c][5].x, 8);
        float ly = __shfl_up_sync(0xffffffffu,   acc[c][5].y, 8);
        float hx = __shfl_down_sync(0xffffffffu, acc[c][0].x, 8);
        float hy = __shfl_down_sync(0xffffffffu, acc[c][0].y, 8);
        tlo[c] = (q > 0) ? make_float2(lx, ly) : z;
        thi[c] = (q < 3) ? make_float2(hx, hy) : z;
    }

    float2 r12[3][6];
    #pragma unroll
    for (int co = 0; co < 3; ++co) {
        float b = __ldg(b2 + co) + __ldg(bd + co);
        #pragma unroll
        for (int j = 0; j < 6; ++j) r12[co][j] = make_float2(b, b);
    }

    #pragma unroll
    for (int ci = 0; ci < 3; ++ci) {
        float2 tv[8];
        tv[0] = tlo[ci];
        #pragma unroll
        for (int j = 0; j < 6; ++j) tv[j + 1] = acc[ci][j];
        tv[7] = thi[ci];

        const float4* cp = (const float4*)(cur + (size_t)ci*NSP + row*D4) + q*3;
        float4 c4[3];
        #pragma unroll
        for (int m = 0; m < 3; ++m) c4[m] = cp[m];
        const float2* cf = reinterpret_cast<const float2*>(c4);

        #pragma unroll
        for (int co = 0; co < 3; ++co) {
            float w0s = __ldg(W2w + (co*3 + ci)*3 + 0);
            float w1s = __ldg(W2w + (co*3 + ci)*3 + 1);
            float w2s = __ldg(W2w + (co*3 + ci)*3 + 2);
            float wds = __ldg(Wdw + co*3 + ci);
            float2 w0 = make_float2(w0s, w0s);
            float2 w1 = make_float2(w1s, w1s);
            float2 w2 = make_float2(w2s, w2s);
            float2 wd = make_float2(wds, wds);
            #pragma unroll
            for (int j = 0; j < 6; ++j) {
                float2 a = r12[co][j];
                a = ffma2(tv[j],     w0, a);
                a = ffma2(tv[j + 1], w1, a);
                a = ffma2(tv[j + 2], w2, a);
                a = ffma2(cf[j],     wd, a);
                r12[co][j] = a;
            }
        }
    }

    if (final_layer) {
        #pragma unroll
        for (int co = 0; co < 3; ++co) {
            float2* o0 = (float2*)(ofinal + (size_t)co*NSP + base);
            float2* o1 = (float2*)(ofinal + CN + (size_t)co*NSP + base);
            #pragma unroll
            for (int m = 0; m < 3; ++m) {
                o0[m] = make_float2(r12[co][2*m].x, r12[co][2*m + 1].x);
                o1[m] = make_float2(r12[co][2*m].y, r12[co][2*m + 1].y);
            }
        }
        return;
    }

    #pragma unroll
    for (int co = 0; co < 3; ++co) {
        float4* op = (float4*)(onew + (size_t)co*NSP + row*D4) + q*3;
        #pragma unroll
        for (int m = 0; m < 3; ++m)
            op[m] = make_float4(r12[co][2*m].x,   r12[co][2*m].y,
                                r12[co][2*m+1].x, r12[co][2*m+1].y);
    }
}

// ---------------------------------------------------------------------------
// Driver
// ---------------------------------------------------------------------------
extern "C" void kernel_launch(void* const* d_in, const int* in_sizes, int n_in,
                              void* d_out, int out_size)
{
    const float* f   = (const float*)d_in[0];
    const float* bnd = (const float*)d_in[1];
    const float* Wg  = (const float*)d_in[2];
    const float* bg  = (const float*)d_in[3];
    const float* W1  = (const float*)d_in[4];
    const float* b1  = (const float*)d_in[5];
    const float* W2  = (const float*)d_in[6];
    const float* b2  = (const float*)d_in[7];
    const float* Wd  = (const float*)d_in[8];
    const float* bd  = (const float*)d_in[9];

    static bool attr_done = false;
    if (!attr_done) {
        cudaFuncSetAttribute(wg2d_kernel,
            cudaFuncAttributeMaxDynamicSharedMemorySize, G2_SMEM);
        cudaFuncSetAttribute(w1f_kernel,
            cudaFuncAttributeMaxDynamicSharedMemorySize, W1_SMEM);
        attr_done = true;
    }

    float2 *fi, *bi, *gg, *oA, *oB, *ub;
    float *w2d;
    cudaGetSymbolAddress((void**)&fi, s_fi);
    cudaGetSymbolAddress((void**)&bi, s_bi);
    cudaGetSymbolAddress((void**)&gg, s_g);
    cudaGetSymbolAddress((void**)&oA, s_oA);
    cudaGetSymbolAddress((void**)&oB, s_oB);
    cudaGetSymbolAddress((void**)&ub, s_u2);
    cudaGetSymbolAddress((void**)&w2d, s_w2d);

    pack_kernel<<<(CN/4 + 255) / 256, 256>>>(
        (const float4*)f, (const float4*)bnd, (float4*)fi, (float4*)bi,
        Wg, w2d);

    // one-time 2-D transforms: f -> u2[0..2], boundary -> u2[3..5]
    bx2_kernel<<<dim3(NCOL, 3), 256>>>(fi, ub);
    bx2_kernel<<<dim3(NCOL, 3), 256>>>(bi, ub + 3*U2ROWS*32);
    // launch order: harness(2) + pack + 2x bx2 => first wg2d in ncu -s 5 slot

    dim3 ggrid(D1/2, D2/8, D3/6);
    dim3 cgrid(D1/2, D2/4, D3/8);
    const float2* cur = fi;
    float2* outs[LAYERS] = {oA, oB, oA, nullptr};

    for (int i = 0; i < LAYERS; ++i) {
        wg2d_kernel<<<ggrid, 512, G2_SMEM>>>(
            ub, w2d + (size_t)i*10368, bg + i*3, gg);
        w1f_kernel<<<cgrid, 256, W1_SMEM>>>(
            gg, cur, W1 + i*243, b1 + i*3, W2 + i*27, b2 + i*3,
            Wd + i*9, bd + i*3,
            outs[i], (float*)d_out, (i == LAYERS - 1) ? 1 : 0);
        if (i < LAYERS - 1)
            bx2_kernel<<<dim3(NCOL, 3), 256>>>(outs[i], ub);
        cur = outs[i];
    }
}